// round 4
// baseline (speedup 1.0000x reference)
#include <cuda_runtime.h>
#include <cstdint>
#include <cstddef>

// ---------------------------------------------------------------------------
// Problem constants
// ---------------------------------------------------------------------------
#define N_INST 2000
#define HDIM   256
#define DDIM   64
#define RDIM   49
#define PARAMS_PER (2 * HDIM * DDIM)      // 32768
#define F2_COLS (RDIM * HDIM)             // 12544
#define KSPLIT 8
#define KCHUNK (F2_COLS / KSPLIT)         // 1568

// Scratch (allowed: __device__ globals, no runtime allocation)
__device__ float g_params[(size_t)N_INST * PARAMS_PER];   // 262 MB
__device__ float g_f2[(size_t)N_INST * F2_COLS];          // 100 MB
__device__ float g_kpart[(size_t)KSPLIT * N_INST * HDIM]; // 16 MB

// ---------------------------------------------------------------------------
// Packed f32x2 helpers (sm_103a: doubles fp32 FMA throughput vs scalar FFMA)
// ---------------------------------------------------------------------------
__device__ __forceinline__ double pk2(float lo, float hi) {
    double d; asm("mov.b64 %0, {%1, %2};" : "=d"(d) : "f"(lo), "f"(hi)); return d;
}
__device__ __forceinline__ double dup2(float a) {
    double d; asm("mov.b64 %0, {%1, %1};" : "=d"(d) : "f"(a)); return d;
}
__device__ __forceinline__ void fma2(double& c, double a, double b) {
    asm("fma.rn.f32x2 %0, %1, %2, %0;" : "+d"(c) : "d"(a), "d"(b));
}
__device__ __forceinline__ float2 upk2(double v) {
    float2 r; asm("mov.b64 {%0, %1}, %2;" : "=f"(r.x), "=f"(r.y) : "d"(v)); return r;
}

__device__ __forceinline__ float warp_sum(float v) {
#pragma unroll
    for (int o = 16; o > 0; o >>= 1) v += __shfl_xor_sync(0xffffffffu, v, o);
    return v;
}

// ---------------------------------------------------------------------------
// SGEMM: C[M x N] = A[M x K] * B[K x N] (+bias), 128x128x16 tiles, 256 thr,
// 8x8 register tile per thread in f32x2 pairs, register-prefetch double buffer,
// optional split-K via blockIdx.z (each z writes its own partial slab of C).
// N tiles must divide evenly (true here: 32768%128==0, 256%128==0).
// ---------------------------------------------------------------------------
__global__ void __launch_bounds__(256, 2)
sgemm128(const float* __restrict__ A, int lda,
         const float* __restrict__ B, int ldb,
         float* __restrict__ C, int ldc,
         int M, int kChunk, int Ktotal,
         const float* __restrict__ bias)
{
    __shared__ float As[16][128];
    __shared__ float Bs[16][128];

    const int tid = threadIdx.x;
    const int tx = tid & 15;      // col group
    const int ty = tid >> 4;      // row group
    const int mBase = blockIdx.y * 128;
    const int nBase = blockIdx.x * 128;

    const int kStart = blockIdx.z * kChunk;
    const int kEnd = min(Ktotal, kStart + kChunk);
    C += (size_t)blockIdx.z * (size_t)M * (size_t)ldc;

    // loader mapping: A tile = 128 rows x 16 k  (512 float4), transposed store
    const int aRow0 = tid >> 2,          aK0 = (tid & 3) * 4;
    const int aRow1 = (tid + 256) >> 2,  aK1 = ((tid + 256) & 3) * 4;
    //                 B tile = 16 k x 128 cols (512 float4), direct store
    const int bK0 = tid >> 5,            bC0 = (tid & 31) * 4;
    const int bK1 = (tid + 256) >> 5,    bC1 = ((tid + 256) & 31) * 4;

    const float4 f4z = make_float4(0.f, 0.f, 0.f, 0.f);

    double acc[8][4];
#pragma unroll
    for (int i = 0; i < 8; i++)
#pragma unroll
        for (int j = 0; j < 4; j++) acc[i][j] = 0.0;

    float4 va0, va1, vb0, vb1;
    {   // prologue load
        int r0 = mBase + aRow0, r1 = mBase + aRow1;
        va0 = (r0 < M) ? *(const float4*)&A[(size_t)r0 * lda + kStart + aK0] : f4z;
        va1 = (r1 < M) ? *(const float4*)&A[(size_t)r1 * lda + kStart + aK1] : f4z;
        vb0 = *(const float4*)&B[(size_t)(kStart + bK0) * ldb + nBase + bC0];
        vb1 = *(const float4*)&B[(size_t)(kStart + bK1) * ldb + nBase + bC1];
    }

    for (int kt = kStart; kt < kEnd; kt += 16) {
        // stage regs -> smem
        As[aK0 + 0][aRow0] = va0.x; As[aK0 + 1][aRow0] = va0.y;
        As[aK0 + 2][aRow0] = va0.z; As[aK0 + 3][aRow0] = va0.w;
        As[aK1 + 0][aRow1] = va1.x; As[aK1 + 1][aRow1] = va1.y;
        As[aK1 + 2][aRow1] = va1.z; As[aK1 + 3][aRow1] = va1.w;
        *(float4*)&Bs[bK0][bC0] = vb0;
        *(float4*)&Bs[bK1][bC1] = vb1;
        __syncthreads();

        const int ktn = kt + 16;
        if (ktn < kEnd) {   // prefetch next tile while computing this one
            int r0 = mBase + aRow0, r1 = mBase + aRow1;
            va0 = (r0 < M) ? *(const float4*)&A[(size_t)r0 * lda + ktn + aK0] : f4z;
            va1 = (r1 < M) ? *(const float4*)&A[(size_t)r1 * lda + ktn + aK1] : f4z;
            vb0 = *(const float4*)&B[(size_t)(ktn + bK0) * ldb + nBase + bC0];
            vb1 = *(const float4*)&B[(size_t)(ktn + bK1) * ldb + nBase + bC1];
        }

#pragma unroll
        for (int k = 0; k < 16; k++) {
            float4 a0 = *(float4*)&As[k][ty * 4];
            float4 a1 = *(float4*)&As[k][64 + ty * 4];
            float4 b0 = *(float4*)&Bs[k][tx * 4];
            float4 b1 = *(float4*)&Bs[k][64 + tx * 4];
            double pb[4] = { pk2(b0.x, b0.y), pk2(b0.z, b0.w),
                             pk2(b1.x, b1.y), pk2(b1.z, b1.w) };
            float av[8] = { a0.x, a0.y, a0.z, a0.w, a1.x, a1.y, a1.z, a1.w };
#pragma unroll
            for (int i = 0; i < 8; i++) {
                double da = dup2(av[i]);
                fma2(acc[i][0], da, pb[0]);
                fma2(acc[i][1], da, pb[1]);
                fma2(acc[i][2], da, pb[2]);
                fma2(acc[i][3], da, pb[3]);
            }
        }
        __syncthreads();
    }

    // epilogue
#pragma unroll
    for (int i = 0; i < 8; i++) {
        int r = mBase + ((i < 4) ? (ty * 4 + i) : (64 + ty * 4 + (i - 4)));
        if (r >= M) continue;
        float2 c01 = upk2(acc[i][0]);
        float2 c23 = upk2(acc[i][1]);
        float2 c45 = upk2(acc[i][2]);
        float2 c67 = upk2(acc[i][3]);
        int cb0 = nBase + tx * 4;
        int cb1 = cb0 + 64;
        if (bias) {
            c01.x += bias[cb0 + 0]; c01.y += bias[cb0 + 1];
            c23.x += bias[cb0 + 2]; c23.y += bias[cb0 + 3];
            c45.x += bias[cb1 + 0]; c45.y += bias[cb1 + 1];
            c67.x += bias[cb1 + 2]; c67.y += bias[cb1 + 3];
        }
        float4 o0 = make_float4(c01.x, c01.y, c23.x, c23.y);
        float4 o1 = make_float4(c45.x, c45.y, c67.x, c67.y);
        *(float4*)&C[(size_t)r * ldc + cb0] = o0;
        *(float4*)&C[(size_t)r * ldc + cb1] = o1;
    }
}

// ---------------------------------------------------------------------------
// Fused per-instance dynamic conv:
//   f1 = feats(49x256) @ p1(256x64);  LN_D + relu
//   f2 = f1(49x64)     @ p2(64x256);  LN_H + relu  -> g_f2[n] (flattened r*256+h)
// One CTA (256 thr) per instance. Everything staged in SMEM.
// ---------------------------------------------------------------------------
#define SF_LD 264   // 256 + 8 pad (conflict-free column reads: 264 % 32 == 8)
#define DC_SF_FLOATS (RDIM * SF_LD)                 // 12936
#define DC_SP_FLOATS (HDIM * DDIM)                  // 16384
#define DC_SX_FLOATS (RDIM * DDIM)                  // 3136
#define DC_SMEM_BYTES ((DC_SF_FLOATS + DC_SP_FLOATS + DC_SX_FLOATS) * 4)  // 129824

__global__ void __launch_bounds__(256)
dynconv_kernel(const float* __restrict__ roi,   // (49, 2000, 256)
               const float* __restrict__ g1, const float* __restrict__ b1,
               const float* __restrict__ g2, const float* __restrict__ b2)
{
    extern __shared__ float sh[];
    float* sF = sh;                              // feats then f2 : 49 x SF_LD
    float* sP = sh + DC_SF_FLOATS;               // p1 then p2    : 16384
    float* sX = sh + DC_SF_FLOATS + DC_SP_FLOATS;// f1            : 49 x 64

    const int n = blockIdx.x;
    const int tid = threadIdx.x;
    const int lane = tid & 31;
    const int warp = tid >> 5;

    // ---- load feats[n] (49 x 256) and p1 (16384) ----
    {
        const float4* prow = (const float4*)(g_params + (size_t)n * PARAMS_PER);
#pragma unroll 1
        for (int i = tid; i < RDIM * 64; i += 256) {           // 3136 float4
            int r = i >> 6, c4 = i & 63;
            const float4* src = (const float4*)(roi + ((size_t)r * N_INST + n) * HDIM);
            ((float4*)(sF + r * SF_LD))[c4] = src[c4];
        }
#pragma unroll 1
        for (int i = tid; i < DC_SP_FLOATS / 4; i += 256)
            ((float4*)sP)[i] = prow[i];
    }
    __syncthreads();

    // ---- bmm1: f1[r][d] = sum_h feats[r][h] * p1[h][d] ----
    {
        const int d0 = (tid & 7) * 8;
        const int r1 = tid >> 3;            // 0..31
        const int r2 = r1 + 32;             // 32..63
        const bool has2 = (r2 < RDIM);
        float a1c[8] = {0,0,0,0,0,0,0,0};
        float a2c[8] = {0,0,0,0,0,0,0,0};
#pragma unroll 4
        for (int h = 0; h < HDIM; h++) {
            float4 b0 = *(float4*)&sP[h * DDIM + d0];
            float4 b1v = *(float4*)&sP[h * DDIM + d0 + 4];
            float a1 = sF[r1 * SF_LD + h];
            float a2 = has2 ? sF[r2 * SF_LD + h] : 0.f;
            a1c[0] = fmaf(a1, b0.x, a1c[0]); a1c[1] = fmaf(a1, b0.y, a1c[1]);
            a1c[2] = fmaf(a1, b0.z, a1c[2]); a1c[3] = fmaf(a1, b0.w, a1c[3]);
            a1c[4] = fmaf(a1, b1v.x, a1c[4]); a1c[5] = fmaf(a1, b1v.y, a1c[5]);
            a1c[6] = fmaf(a1, b1v.z, a1c[6]); a1c[7] = fmaf(a1, b1v.w, a1c[7]);
            a2c[0] = fmaf(a2, b0.x, a2c[0]); a2c[1] = fmaf(a2, b0.y, a2c[1]);
            a2c[2] = fmaf(a2, b0.z, a2c[2]); a2c[3] = fmaf(a2, b0.w, a2c[3]);
            a2c[4] = fmaf(a2, b1v.x, a2c[4]); a2c[5] = fmaf(a2, b1v.y, a2c[5]);
            a2c[6] = fmaf(a2, b1v.z, a2c[6]); a2c[7] = fmaf(a2, b1v.w, a2c[7]);
        }
        *(float4*)&sX[r1 * DDIM + d0]     = make_float4(a1c[0], a1c[1], a1c[2], a1c[3]);
        *(float4*)&sX[r1 * DDIM + d0 + 4] = make_float4(a1c[4], a1c[5], a1c[6], a1c[7]);
        if (has2) {
            *(float4*)&sX[r2 * DDIM + d0]     = make_float4(a2c[0], a2c[1], a2c[2], a2c[3]);
            *(float4*)&sX[r2 * DDIM + d0 + 4] = make_float4(a2c[4], a2c[5], a2c[6], a2c[7]);
        }
    }
    __syncthreads();

    // ---- load p2 (overwrites sP; bmm1 done) ----
    {
        const float4* prow = (const float4*)(g_params + (size_t)n * PARAMS_PER + HDIM * DDIM);
#pragma unroll 1
        for (int i = tid; i < DC_SP_FLOATS / 4; i += 256)
            ((float4*)sP)[i] = prow[i];
    }

    // ---- LN over D=64 + relu, in place on sX ----
    {
        float gg0 = g1[lane], gg1 = g1[lane + 32];
        float bb0 = b1[lane], bb1 = b1[lane + 32];
        for (int r = warp; r < RDIM; r += 8) {
            float v0 = sX[r * DDIM + lane];
            float v1 = sX[r * DDIM + lane + 32];
            float s = warp_sum(v0 + v1);
            float sq = warp_sum(v0 * v0 + v1 * v1);
            float m = s * (1.f / DDIM);
            float var = sq * (1.f / DDIM) - m * m;
            float inv = rsqrtf(var + 1e-5f);
            sX[r * DDIM + lane]      = fmaxf((v0 - m) * inv * gg0 + bb0, 0.f);
            sX[r * DDIM + lane + 32] = fmaxf((v1 - m) * inv * gg1 + bb1, 0.f);
        }
    }
    __syncthreads();

    // ---- bmm2: f2[r][h] = sum_d f1[r][d] * p2[d][h]  -> sF ----
    {
        const int h0 = (tid & 31) * 8;
        const int rb = tid >> 5;            // 0..7
#pragma unroll 1
        for (int p = 0; p < 4; p++) {
            int r1 = rb + 16 * p;
            if (r1 >= RDIM) break;
            int r2 = r1 + 8;
            bool has2 = (r2 < RDIM);
            float a1c[8] = {0,0,0,0,0,0,0,0};
            float a2c[8] = {0,0,0,0,0,0,0,0};
#pragma unroll 4
            for (int k = 0; k < DDIM; k++) {
                float4 b0 = *(float4*)&sP[k * HDIM + h0];
                float4 b1v = *(float4*)&sP[k * HDIM + h0 + 4];
                float a1 = sX[r1 * DDIM + k];
                float a2 = has2 ? sX[r2 * DDIM + k] : 0.f;
                a1c[0] = fmaf(a1, b0.x, a1c[0]); a1c[1] = fmaf(a1, b0.y, a1c[1]);
                a1c[2] = fmaf(a1, b0.z, a1c[2]); a1c[3] = fmaf(a1, b0.w, a1c[3]);
                a1c[4] = fmaf(a1, b1v.x, a1c[4]); a1c[5] = fmaf(a1, b1v.y, a1c[5]);
                a1c[6] = fmaf(a1, b1v.z, a1c[6]); a1c[7] = fmaf(a1, b1v.w, a1c[7]);
                a2c[0] = fmaf(a2, b0.x, a2c[0]); a2c[1] = fmaf(a2, b0.y, a2c[1]);
                a2c[2] = fmaf(a2, b0.z, a2c[2]); a2c[3] = fmaf(a2, b0.w, a2c[3]);
                a2c[4] = fmaf(a2, b1v.x, a2c[4]); a2c[5] = fmaf(a2, b1v.y, a2c[5]);
                a2c[6] = fmaf(a2, b1v.z, a2c[6]); a2c[7] = fmaf(a2, b1v.w, a2c[7]);
            }
#pragma unroll
            for (int j = 0; j < 8; j++) sF[r1 * SF_LD + h0 + j] = a1c[j];
            if (has2) {
#pragma unroll
                for (int j = 0; j < 8; j++) sF[r2 * SF_LD + h0 + j] = a2c[j];
            }
        }
    }
    __syncthreads();

    // ---- LN over H=256 + relu, write flattened to g_f2[n] ----
    {
        float gA[8], bA[8];
#pragma unroll
        for (int j = 0; j < 8; j++) { gA[j] = g2[lane + 32 * j]; bA[j] = b2[lane + 32 * j]; }
        float* dst = g_f2 + (size_t)n * F2_COLS;
        for (int r = warp; r < RDIM; r += 8) {
            float v[8];
            float s = 0.f, sq = 0.f;
#pragma unroll
            for (int j = 0; j < 8; j++) {
                v[j] = sF[r * SF_LD + lane + 32 * j];
                s += v[j]; sq += v[j] * v[j];
            }
            s = warp_sum(s); sq = warp_sum(sq);
            float m = s * (1.f / HDIM);
            float var = sq * (1.f / HDIM) - m * m;
            float inv = rsqrtf(var + 1e-5f);
#pragma unroll
            for (int j = 0; j < 8; j++) {
                int h = lane + 32 * j;
                dst[r * HDIM + h] = fmaxf((v[j] - m) * inv * gA[j] + bA[j], 0.f);
            }
        }
    }
}

// ---------------------------------------------------------------------------
// Reduce split-K partials + bias, LN over H=256 + relu -> output (2000 x 256)
// ---------------------------------------------------------------------------
__global__ void __launch_bounds__(256)
reduce_ln3(const float* __restrict__ b_out,
           const float* __restrict__ g3, const float* __restrict__ b3,
           float* __restrict__ out)
{
    const int lane = threadIdx.x & 31;
    const int warp = threadIdx.x >> 5;
    const int row = blockIdx.x * 8 + warp;          // grid 250 * 8 = 2000
    float v[8];
    float s = 0.f, sq = 0.f;
#pragma unroll
    for (int j = 0; j < 8; j++) {
        int h = lane + 32 * j;
        float a = b_out[h];
#pragma unroll
        for (int z = 0; z < KSPLIT; z++)
            a += g_kpart[((size_t)z * N_INST + row) * HDIM + h];
        v[j] = a; s += a; sq += a * a;
    }
    s = warp_sum(s); sq = warp_sum(sq);
    float m = s * (1.f / HDIM);
    float var = sq * (1.f / HDIM) - m * m;
    float inv = rsqrtf(var + 1e-5f);
#pragma unroll
    for (int j = 0; j < 8; j++) {
        int h = lane + 32 * j;
        float o = (v[j] - m) * inv * g3[h] + b3[h];
        out[(size_t)row * HDIM + h] = fmaxf(o, 0.f);
    }
}

// ---------------------------------------------------------------------------
extern "C" void kernel_launch(void* const* d_in, const int* in_sizes, int n_in,
                              void* d_out, int out_size)
{
    (void)in_sizes; (void)n_in; (void)out_size;
    const float* pro   = (const float*)d_in[0];   // (1, 2000, 256)
    const float* roi   = (const float*)d_in[1];   // (49, 2000, 256)
    const float* W_dyn = (const float*)d_in[2];   // (256, 32768)
    const float* b_dyn = (const float*)d_in[3];   // (32768,)
    const float* W_out = (const float*)d_in[4];   // (12544, 256)
    const float* b_out = (const float*)d_in[5];   // (256,)
    const float* g1 = (const float*)d_in[6];
    const float* b1 = (const float*)d_in[7];
    const float* g2 = (const float*)d_in[8];
    const float* b2 = (const float*)d_in[9];
    const float* g3 = (const float*)d_in[10];
    const float* b3 = (const float*)d_in[11];
    float* out = (float*)d_out;

    float *p_params = nullptr, *p_f2 = nullptr, *p_kpart = nullptr;
    cudaGetSymbolAddress((void**)&p_params, g_params);
    cudaGetSymbolAddress((void**)&p_f2, g_f2);
    cudaGetSymbolAddress((void**)&p_kpart, g_kpart);

    cudaFuncSetAttribute(dynconv_kernel,
                         cudaFuncAttributeMaxDynamicSharedMemorySize, DC_SMEM_BYTES);

    // K1: params = pro @ W_dyn + b_dyn            (2000 x 32768, K=256)
    sgemm128<<<dim3(PARAMS_PER / 128, 16, 1), 256>>>(
        pro, HDIM, W_dyn, PARAMS_PER, p_params, PARAMS_PER,
        N_INST, HDIM, HDIM, b_dyn);

    // K2: fused per-instance dynamic conv -> g_f2 (2000 x 12544)
    dynconv_kernel<<<N_INST, 256, DC_SMEM_BYTES>>>(roi, g1, b1, g2, b2);

    // K3: partials of F2 @ W_out, split-K=8       (2000 x 256, K=12544)
    sgemm128<<<dim3(HDIM / 128, 16, KSPLIT), 256>>>(
        p_f2, F2_COLS, W_out, HDIM, p_kpart, HDIM,
        N_INST, KCHUNK, F2_COLS, nullptr);

    // K4: reduce partials + bias + LN + relu -> out
    reduce_ln3<<<N_INST / 8, 256>>>(b_out, g3, b3, out);
}

// round 6
// speedup vs baseline: 1.3014x; 1.3014x over previous
#include <cuda_runtime.h>
#include <cuda_bf16.h>
#include <cstdint>
#include <cstddef>

#define N_INST 2000
#define MPAD   2048
#define HDIM   256
#define DDIM   64
#define RDIM   49
#define PARAMS_PER 32768
#define F2_COLS 12544
#define KSPL 14
#define KPERZ (F2_COLS / KSPL)   // 896

// Scratch: __device__ globals (zero-initialized; padded rows [2000,2048) of the
// bf16 A-operands are never written -> stay zero -> no edge predication).
__device__ __align__(256) float g_params[(size_t)MPAD * PARAMS_PER];
__device__ __align__(256) __nv_bfloat16 g_proh[MPAD * HDIM];
__device__ __align__(256) __nv_bfloat16 g_prol[MPAD * HDIM];
__device__ __align__(256) __nv_bfloat16 g_wdh[(size_t)PARAMS_PER * HDIM];
__device__ __align__(256) __nv_bfloat16 g_wdl[(size_t)PARAMS_PER * HDIM];
__device__ __align__(256) __nv_bfloat16 g_woh[(size_t)HDIM * F2_COLS];
__device__ __align__(256) __nv_bfloat16 g_wol[(size_t)HDIM * F2_COLS];
__device__ __align__(256) __nv_bfloat16 g_f2h[(size_t)MPAD * F2_COLS];
__device__ __align__(256) __nv_bfloat16 g_f2l[(size_t)MPAD * F2_COLS];
__device__ __align__(256) float g_kpart[(size_t)KSPL * MPAD * HDIM];

// ---------------- small helpers ----------------
__device__ __forceinline__ float warp_sum(float v) {
#pragma unroll
    for (int o = 16; o > 0; o >>= 1) v += __shfl_xor_sync(0xffffffffu, v, o);
    return v;
}
__device__ __forceinline__ void bfsplit(float x, __nv_bfloat16& h, __nv_bfloat16& l) {
    h = __float2bfloat16(x);
    l = __float2bfloat16(x - __bfloat162float(h));
}
__device__ __forceinline__ uint32_t smem_u32(const void* p) {
    uint32_t a;
    asm("{ .reg .u64 t; cvta.to.shared.u64 t, %1; cvt.u32.u64 %0, t; }" : "=r"(a) : "l"(p));
    return a;
}
#define CP16(dst, src) asm volatile( \
    "cp.async.cg.shared.global [%0], [%1], 16;" :: "r"(dst), "l"(src) : "memory")
#define CP_COMMIT() asm volatile("cp.async.commit_group;" ::: "memory")
#define CP_WAIT2()  asm volatile("cp.async.wait_group 2;" ::: "memory")

// mma.sync m16n8k16 row.col f32.bf16.bf16.f32 (compute_103-portable HMMA path)
#define MMA16816(c, a, b) asm volatile( \
    "mma.sync.aligned.m16n8k16.row.col.f32.bf16.bf16.f32 " \
    "{%0,%1,%2,%3}, {%4,%5,%6,%7}, {%8,%9}, {%0,%1,%2,%3};" \
    : "+f"((c)[0]), "+f"((c)[1]), "+f"((c)[2]), "+f"((c)[3]) \
    : "r"((a)[0]), "r"((a)[1]), "r"((a)[2]), "r"((a)[3]), "r"((b)[0]), "r"((b)[1]))

// ---------------------------------------------------------------------------
// Prep: split pro into bf16 hi/lo
// ---------------------------------------------------------------------------
__global__ void prep_pro(const float* __restrict__ pro) {
    int i = blockIdx.x * 256 + threadIdx.x;
    if (i >= N_INST * HDIM) return;
    bfsplit(pro[i], g_proh[i], g_prol[i]);
}

// Prep: transpose f32 src(K x N) -> hi/lo bf16 dst(N x K). K,N multiples of 32.
__global__ void __launch_bounds__(256)
prep_trans(const float* __restrict__ src, __nv_bfloat16* __restrict__ dh,
           __nv_bfloat16* __restrict__ dl, int K, int N) {
    __shared__ float t[32][33];
    const int kb = blockIdx.y * 32, nb = blockIdx.x * 32;
    const int tx = threadIdx.x & 31, ty = threadIdx.x >> 5;   // 32 x 8
#pragma unroll
    for (int j = 0; j < 32; j += 8)
        t[ty + j][tx] = src[(size_t)(kb + ty + j) * N + nb + tx];
    __syncthreads();
#pragma unroll
    for (int j = 0; j < 32; j += 8) {
        float x = t[tx][ty + j];
        size_t o = (size_t)(nb + ty + j) * K + kb + tx;
        bfsplit(x, dh[o], dl[o]);
    }
}

// ---------------------------------------------------------------------------
// bf16 mma.sync GEMM, 3-pass hi/lo: C = Ah@Bh^T + Ah@Bl^T + Al@Bh^T (+bias)
// A*: (MPAD x lda) K-major rows. B*: (Ntot x ldb) K-major rows (row = out col).
// 128x128x32 CTA tile, 8 warps (2x4) x (64x32) warp tile, 4-stage cp.async.
// Split-K via blockIdx.z: kOff = z*kLen, C += z*zStride.
// ---------------------------------------------------------------------------
#define LDT   40                      // smem row stride in bf16 (80B: 16B-aligned, conflict-free)
#define TILEB (128 * LDT * 2)         // 10240 B per tile
#define STGB  (2 * TILEB)             // A + B per stage
#define NSTG  4
#define GM_SMEM (NSTG * STGB)         // 81920 B

__global__ void __launch_bounds__(256, 2)
gemm_mma(const __nv_bfloat16* __restrict__ Ah, const __nv_bfloat16* __restrict__ Al, int lda,
         const __nv_bfloat16* __restrict__ Bh, const __nv_bfloat16* __restrict__ Bl, int ldb,
         float* __restrict__ C, int ldc, size_t zStride, int kLen,
         const float* __restrict__ bias)
{
    extern __shared__ char sm[];
    const uint32_t sb = smem_u32(sm);
    const int tid = threadIdx.x;
    const int wid = tid >> 5, lane = tid & 31;
    const int lg = lane >> 2, tg = lane & 3;      // group / thread-in-group
    const int wm = wid & 1, wn = wid >> 1;        // 2 x 4 warp grid
    const int mBase = blockIdx.y * 128, nBase = blockIdx.x * 128;
    const int kOff = blockIdx.z * kLen;
    C += (size_t)blockIdx.z * zStride;

    const int nCh = kLen >> 5;                    // 32-wide K chunks
    const int T = 3 * nCh;

    // loader state: row/k8 handled per thread, cursor over (pass, chunk)
    const int lrow = tid >> 2, lk8 = (tid & 3);   // thread loads rows lrow (A) & lrow (B), 2 chunks... 
    // each thread issues 2 A + 2 B cp.asyncs: indices tid and tid+256
    int lp = 0, lc = 0;

    auto issue = [&](int slot) {
        const __nv_bfloat16* A = (lp < 2) ? Ah : Al;
        const __nv_bfloat16* B = (lp == 1) ? Bl : Bh;
        const int kpos = kOff + lc * 32;
        const uint32_t stg = sb + slot * STGB;
#pragma unroll
        for (int j = 0; j < 2; j++) {
            int idx = tid + 256 * j;
            int row = idx >> 2, k8 = idx & 3;
            const __nv_bfloat16* sa = A + (size_t)(mBase + row) * lda + kpos + k8 * 8;
            const __nv_bfloat16* sbp = B + (size_t)(nBase + row) * ldb + kpos + k8 * 8;
            CP16(stg + row * 80 + k8 * 16, sa);
            CP16(stg + TILEB + row * 80 + k8 * 16, sbp);
        }
        if (++lc == nCh) { lc = 0; ++lp; }
    };
    (void)lrow; (void)lk8;

    float acc[4][4][4];
#pragma unroll
    for (int i = 0; i < 4; i++)
#pragma unroll
        for (int j = 0; j < 4; j++)
#pragma unroll
            for (int k = 0; k < 4; k++) acc[i][j][k] = 0.f;

    // prologue: fill NSTG-1 stages
#pragma unroll
    for (int s = 0; s < NSTG - 1; s++) {
        if (lp < 3) issue(s);
        CP_COMMIT();
    }

    for (int g = 0; g < T; g++) {
        CP_WAIT2();
        __syncthreads();
        if (lp < 3) issue((g + NSTG - 1) & (NSTG - 1));
        CP_COMMIT();

        const char* stg = sm + (g & (NSTG - 1)) * STGB;
        const char* aT = stg;
        const char* bT = stg + TILEB;
#pragma unroll
        for (int ks = 0; ks < 2; ks++) {
            uint32_t af[4][4], bf_[4][2];
#pragma unroll
            for (int mf = 0; mf < 4; mf++) {
                const char* p = aT + (wm * 64 + mf * 16 + lg) * 80 + ks * 32 + tg * 4;
                af[mf][0] = *(const uint32_t*)p;
                af[mf][1] = *(const uint32_t*)(p + 640);   // row +8
                af[mf][2] = *(const uint32_t*)(p + 16);    // k +8
                af[mf][3] = *(const uint32_t*)(p + 656);
            }
#pragma unroll
            for (int nf = 0; nf < 4; nf++) {
                const char* q = bT + (wn * 32 + nf * 8 + lg) * 80 + ks * 32 + tg * 4;
                bf_[nf][0] = *(const uint32_t*)q;
                bf_[nf][1] = *(const uint32_t*)(q + 16);   // k +8
            }
#pragma unroll
            for (int mf = 0; mf < 4; mf++)
#pragma unroll
                for (int nf = 0; nf < 4; nf++)
                    MMA16816(acc[mf][nf], af[mf], bf_[nf]);
        }
    }

    // epilogue: d0,d1 = (row lg, col 2tg / 2tg+1); d2,d3 = (row lg+8, same cols)
#pragma unroll
    for (int mf = 0; mf < 4; mf++) {
        int r0 = mBase + wm * 64 + mf * 16 + lg;
        int r1 = r0 + 8;
#pragma unroll
        for (int nf = 0; nf < 4; nf++) {
            int col = nBase + wn * 32 + nf * 8 + 2 * tg;
            float b0 = 0.f, b1 = 0.f;
            if (bias) { b0 = bias[col]; b1 = bias[col + 1]; }
            float2 v0 = make_float2(acc[mf][nf][0] + b0, acc[mf][nf][1] + b1);
            float2 v1 = make_float2(acc[mf][nf][2] + b0, acc[mf][nf][3] + b1);
            *(float2*)&C[(size_t)r0 * ldc + col] = v0;
            *(float2*)&C[(size_t)r1 * ldc + col] = v1;
        }
    }
}

// ---------------------------------------------------------------------------
// Fused per-instance dynamic conv (proven round-3 math; emits f2 bf16 hi/lo)
// ---------------------------------------------------------------------------
#define SF_LD 264
#define DC_SF_FLOATS (RDIM * SF_LD)
#define DC_SP_FLOATS (HDIM * DDIM)
#define DC_SX_FLOATS (RDIM * DDIM)
#define DC_SMEM_BYTES ((DC_SF_FLOATS + DC_SP_FLOATS + DC_SX_FLOATS) * 4)

__global__ void __launch_bounds__(256)
dynconv_kernel(const float* __restrict__ roi,
               const float* __restrict__ g1, const float* __restrict__ b1,
               const float* __restrict__ g2, const float* __restrict__ b2)
{
    extern __shared__ float sh[];
    float* sF = sh;
    float* sP = sh + DC_SF_FLOATS;
    float* sX = sh + DC_SF_FLOATS + DC_SP_FLOATS;

    const int n = blockIdx.x;
    const int tid = threadIdx.x;
    const int lane = tid & 31;
    const int warp = tid >> 5;

    {
        const float4* prow = (const float4*)(g_params + (size_t)n * PARAMS_PER);
#pragma unroll 1
        for (int i = tid; i < RDIM * 64; i += 256) {
            int r = i >> 6, c4 = i & 63;
            const float4* src = (const float4*)(roi + ((size_t)r * N_INST + n) * HDIM);
            ((float4*)(sF + r * SF_LD))[c4] = src[c4];
        }
#pragma unroll 1
        for (int i = tid; i < DC_SP_FLOATS / 4; i += 256)
            ((float4*)sP)[i] = prow[i];
    }
    __syncthreads();

    {   // bmm1
        const int d0 = (tid & 7) * 8;
        const int r1 = tid >> 3, r2 = r1 + 32;
        const bool has2 = (r2 < RDIM);
        float a1c[8] = {0,0,0,0,0,0,0,0};
        float a2c[8] = {0,0,0,0,0,0,0,0};
#pragma unroll 4
        for (int h = 0; h < HDIM; h++) {
            float4 b0 = *(float4*)&sP[h * DDIM + d0];
            float4 b1v = *(float4*)&sP[h * DDIM + d0 + 4];
            float a1 = sF[r1 * SF_LD + h];
            float a2 = has2 ? sF[r2 * SF_LD + h] : 0.f;
            a1c[0] = fmaf(a1, b0.x, a1c[0]); a1c[1] = fmaf(a1, b0.y, a1c[1]);
            a1c[2] = fmaf(a1, b0.z, a1c[2]); a1c[3] = fmaf(a1, b0.w, a1c[3]);
            a1c[4] = fmaf(a1, b1v.x, a1c[4]); a1c[5] = fmaf(a1, b1v.y, a1c[5]);
            a1c[6] = fmaf(a1, b1v.z, a1c[6]); a1c[7] = fmaf(a1, b1v.w, a1c[7]);
            a2c[0] = fmaf(a2, b0.x, a2c[0]); a2c[1] = fmaf(a2, b0.y, a2c[1]);
            a2c[2] = fmaf(a2, b0.z, a2c[2]); a2c[3] = fmaf(a2, b0.w, a2c[3]);
            a2c[4] = fmaf(a2, b1v.x, a2c[4]); a2c[5] = fmaf(a2, b1v.y, a2c[5]);
            a2c[6] = fmaf(a2, b1v.z, a2c[6]); a2c[7] = fmaf(a2, b1v.w, a2c[7]);
        }
        *(float4*)&sX[r1 * DDIM + d0]     = make_float4(a1c[0], a1c[1], a1c[2], a1c[3]);
        *(float4*)&sX[r1 * DDIM + d0 + 4] = make_float4(a1c[4], a1c[5], a1c[6], a1c[7]);
        if (has2) {
            *(float4*)&sX[r2 * DDIM + d0]     = make_float4(a2c[0], a2c[1], a2c[2], a2c[3]);
            *(float4*)&sX[r2 * DDIM + d0 + 4] = make_float4(a2c[4], a2c[5], a2c[6], a2c[7]);
        }
    }
    __syncthreads();

    {   // load p2
        const float4* prow = (const float4*)(g_params + (size_t)n * PARAMS_PER + HDIM * DDIM);
#pragma unroll 1
        for (int i = tid; i < DC_SP_FLOATS / 4; i += 256)
            ((float4*)sP)[i] = prow[i];
    }

    {   // LN over D + relu
        float gg0 = g1[lane], gg1 = g1[lane + 32];
        float bb0 = b1[lane], bb1 = b1[lane + 32];
        for (int r = warp; r < RDIM; r += 8) {
            float v0 = sX[r * DDIM + lane];
            float v1 = sX[r * DDIM + lane + 32];
            float s = warp_sum(v0 + v1);
            float sq = warp_sum(v0 * v0 + v1 * v1);
            float m = s * (1.f / DDIM);
            float var = sq * (1.f / DDIM) - m * m;
            float inv = rsqrtf(var + 1e-5f);
            sX[r * DDIM + lane]      = fmaxf((v0 - m) * inv * gg0 + bb0, 0.f);
            sX[r * DDIM + lane + 32] = fmaxf((v1 - m) * inv * gg1 + bb1, 0.f);
        }
    }
    __syncthreads();

    {   // bmm2 -> sF
        const int h0 = (tid & 31) * 8;
        const int rb = tid >> 5;
#pragma unroll 1
        for (int p = 0; p < 4; p++) {
            int r1 = rb + 16 * p;
            if (r1 >= RDIM) break;
            int r2 = r1 + 8;
            bool has2 = (r2 < RDIM);
            float a1c[8] = {0,0,0,0,0,0,0,0};
            float a2c[8] = {0,0,0,0,0,0,0,0};
#pragma unroll 4
            for (int k = 0; k < DDIM; k++) {
                float4 b0 = *(float4*)&sP[k * HDIM + h0];
                float4 b1v = *(float4*)&sP[k * HDIM + h0 + 4];
                float a1 = sX[r1 * DDIM + k];
                float a2 = has2 ? sX[r2 * DDIM + k] : 0.f;
                a1c[0] = fmaf(a1, b0.x, a1c[0]); a1c[1] = fmaf(a1, b0.y, a1c[1]);
                a1c[2] = fmaf(a1, b0.z, a1c[2]); a1c[3] = fmaf(a1, b0.w, a1c[3]);
                a1c[4] = fmaf(a1, b1v.x, a1c[4]); a1c[5] = fmaf(a1, b1v.y, a1c[5]);
                a1c[6] = fmaf(a1, b1v.z, a1c[6]); a1c[7] = fmaf(a1, b1v.w, a1c[7]);
                a2c[0] = fmaf(a2, b0.x, a2c[0]); a2c[1] = fmaf(a2, b0.y, a2c[1]);
                a2c[2] = fmaf(a2, b0.z, a2c[2]); a2c[3] = fmaf(a2, b0.w, a2c[3]);
                a2c[4] = fmaf(a2, b1v.x, a2c[4]); a2c[5] = fmaf(a2, b1v.y, a2c[5]);
                a2c[6] = fmaf(a2, b1v.z, a2c[6]); a2c[7] = fmaf(a2, b1v.w, a2c[7]);
            }
#pragma unroll
            for (int j = 0; j < 8; j++) sF[r1 * SF_LD + h0 + j] = a1c[j];
            if (has2) {
#pragma unroll
                for (int j = 0; j < 8; j++) sF[r2 * SF_LD + h0 + j] = a2c[j];
            }
        }
    }
    __syncthreads();

    {   // LN over H + relu -> g_f2h/g_f2l (bf16 hi/lo)
        float gA[8], bA[8];
#pragma unroll
        for (int j = 0; j < 8; j++) { gA[j] = g2[lane + 32 * j]; bA[j] = b2[lane + 32 * j]; }
        __nv_bfloat16* dh = g_f2h + (size_t)n * F2_COLS;
        __nv_bfloat16* dl = g_f2l + (size_t)n * F2_COLS;
        for (int r = warp; r < RDIM; r += 8) {
            float v[8];
            float s = 0.f, sq = 0.f;
#pragma unroll
            for (int j = 0; j < 8; j++) {
                v[j] = sF[r * SF_LD + lane + 32 * j];
                s += v[j]; sq += v[j] * v[j];
            }
            s = warp_sum(s); sq = warp_sum(sq);
            float m = s * (1.f / HDIM);
            float var = sq * (1.f / HDIM) - m * m;
            float inv = rsqrtf(var + 1e-5f);
#pragma unroll
            for (int j = 0; j < 8; j++) {
                int h = lane + 32 * j;
                float o = fmaxf((v[j] - m) * inv * gA[j] + bA[j], 0.f);
                bfsplit(o, dh[r * HDIM + h], dl[r * HDIM + h]);
            }
        }
    }
}

// ---------------------------------------------------------------------------
// Reduce split-K partials + bias, LN over H + relu -> out (2000 x 256)
// ---------------------------------------------------------------------------
__global__ void __launch_bounds__(256)
reduce_ln3(const float* __restrict__ b_out,
           const float* __restrict__ g3, const float* __restrict__ b3,
           float* __restrict__ out)
{
    const int lane = threadIdx.x & 31;
    const int warp = threadIdx.x >> 5;
    const int row = blockIdx.x * 8 + warp;
    float v[8];
    float s = 0.f, sq = 0.f;
#pragma unroll
    for (int j = 0; j < 8; j++) {
        int h = lane + 32 * j;
        float a = b_out[h];
#pragma unroll
        for (int z = 0; z < KSPL; z++)
            a += g_kpart[((size_t)z * MPAD + row) * HDIM + h];
        v[j] = a; s += a; sq += a * a;
    }
    s = warp_sum(s); sq = warp_sum(sq);
    float m = s * (1.f / HDIM);
    float var = sq * (1.f / HDIM) - m * m;
    float inv = rsqrtf(var + 1e-5f);
#pragma unroll
    for (int j = 0; j < 8; j++) {
        int h = lane + 32 * j;
        float o = (v[j] - m) * inv * g3[h] + b3[h];
        out[(size_t)row * HDIM + h] = fmaxf(o, 0.f);
    }
}

// ---------------------------------------------------------------------------
extern "C" void kernel_launch(void* const* d_in, const int* in_sizes, int n_in,
                              void* d_out, int out_size)
{
    (void)in_sizes; (void)n_in; (void)out_size;
    const float* pro   = (const float*)d_in[0];
    const float* roi   = (const float*)d_in[1];
    const float* W_dyn = (const float*)d_in[2];
    const float* b_dyn = (const float*)d_in[3];
    const float* W_out = (const float*)d_in[4];
    const float* b_out = (const float*)d_in[5];
    const float* g1 = (const float*)d_in[6];
    const float* b1 = (const float*)d_in[7];
    const float* g2 = (const float*)d_in[8];
    const float* b2 = (const float*)d_in[9];
    const float* g3 = (const float*)d_in[10];
    const float* b3 = (const float*)d_in[11];
    float* out = (float*)d_out;

    float *p_params = nullptr, *p_kpart = nullptr;
    __nv_bfloat16 *p_proh, *p_prol, *p_wdh, *p_wdl, *p_woh, *p_wol, *p_f2h, *p_f2l;
    cudaGetSymbolAddress((void**)&p_params, g_params);
    cudaGetSymbolAddress((void**)&p_kpart, g_kpart);
    cudaGetSymbolAddress((void**)&p_proh, g_proh);
    cudaGetSymbolAddress((void**)&p_prol, g_prol);
    cudaGetSymbolAddress((void**)&p_wdh, g_wdh);
    cudaGetSymbolAddress((void**)&p_wdl, g_wdl);
    cudaGetSymbolAddress((void**)&p_woh, g_woh);
    cudaGetSymbolAddress((void**)&p_wol, g_wol);
    cudaGetSymbolAddress((void**)&p_f2h, g_f2h);
    cudaGetSymbolAddress((void**)&p_f2l, g_f2l);

    cudaFuncSetAttribute(dynconv_kernel,
                         cudaFuncAttributeMaxDynamicSharedMemorySize, DC_SMEM_BYTES);
    cudaFuncSetAttribute(gemm_mma,
                         cudaFuncAttributeMaxDynamicSharedMemorySize, GM_SMEM);

    // P0: hi/lo splits + K-major transposes
    prep_pro<<<(N_INST * HDIM + 255) / 256, 256>>>(pro);
    prep_trans<<<dim3(PARAMS_PER / 32, HDIM / 32), 256>>>(W_dyn, p_wdh, p_wdl, HDIM, PARAMS_PER);
    prep_trans<<<dim3(HDIM / 32, F2_COLS / 32), 256>>>(W_out, p_woh, p_wol, F2_COLS, HDIM);

    // K1: params = pro @ W_dyn + b_dyn   (mma.sync bf16, 3-pass)
    gemm_mma<<<dim3(PARAMS_PER / 128, MPAD / 128, 1), 256, GM_SMEM>>>(
        p_proh, p_prol, HDIM, p_wdh, p_wdl, HDIM,
        p_params, PARAMS_PER, 0, HDIM, b_dyn);

    // K2: fused dynamic conv -> f2 hi/lo
    dynconv_kernel<<<N_INST, 256, DC_SMEM_BYTES>>>(roi, g1, b1, g2, b2);

    // K3: partials of F2 @ W_out, split-K=14 (mma.sync bf16, 3-pass)
    gemm_mma<<<dim3(HDIM / 128, MPAD / 128, KSPL), 256, GM_SMEM>>>(
        p_f2h, p_f2l, F2_COLS, p_woh, p_wol, F2_COLS,
        p_kpart, HDIM, (size_t)MPAD * HDIM, KPERZ, nullptr);

    // K4: reduce + bias + LN + relu -> out
    reduce_ln3<<<N_INST / 8, 256>>>(b_out, g3, b3, out);
}

// round 7
// speedup vs baseline: 1.3062x; 1.0037x over previous
#include <cuda_runtime.h>
#include <cuda_bf16.h>
#include <cstdint>
#include <cstddef>

#define N_INST 2000
#define MPAD   2048
#define HDIM   256
#define DDIM   64
#define RDIM   49
#define PARAMS_PER 32768
#define F2_COLS 12544
#define KSPL 14
#define KPERZ (F2_COLS / KSPL)   // 896

// Scratch: __device__ globals (zero-initialized; padded rows [2000,2048) of the
// bf16 A-operands are never written -> stay zero -> no edge predication).
__device__ __align__(256) float g_params[(size_t)MPAD * PARAMS_PER];
__device__ __align__(256) __nv_bfloat16 g_proh[MPAD * HDIM];
__device__ __align__(256) __nv_bfloat16 g_prol[MPAD * HDIM];
__device__ __align__(256) __nv_bfloat16 g_wdh[(size_t)PARAMS_PER * HDIM];
__device__ __align__(256) __nv_bfloat16 g_wdl[(size_t)PARAMS_PER * HDIM];
__device__ __align__(256) __nv_bfloat16 g_woh[(size_t)HDIM * F2_COLS];
__device__ __align__(256) __nv_bfloat16 g_wol[(size_t)HDIM * F2_COLS];
__device__ __align__(256) __nv_bfloat16 g_f2h[(size_t)MPAD * F2_COLS];
__device__ __align__(256) __nv_bfloat16 g_f2l[(size_t)MPAD * F2_COLS];
__device__ __align__(256) float g_kpart[(size_t)KSPL * MPAD * HDIM];

// ---------------- small helpers ----------------
__device__ __forceinline__ float warp_sum(float v) {
#pragma unroll
    for (int o = 16; o > 0; o >>= 1) v += __shfl_xor_sync(0xffffffffu, v, o);
    return v;
}
__device__ __forceinline__ void bfsplit(float x, __nv_bfloat16& h, __nv_bfloat16& l) {
    h = __float2bfloat16(x);
    l = __float2bfloat16(x - __bfloat162float(h));
}
__device__ __forceinline__ uint32_t smem_u32(const void* p) {
    uint32_t a;
    asm("{ .reg .u64 t; cvta.to.shared.u64 t, %1; cvt.u32.u64 %0, t; }" : "=r"(a) : "l"(p));
    return a;
}
#define CP16(dst, src) asm volatile( \
    "cp.async.cg.shared.global [%0], [%1], 16;" :: "r"(dst), "l"(src) : "memory")
#define CP_COMMIT() asm volatile("cp.async.commit_group;" ::: "memory")
#define CP_WAIT2()  asm volatile("cp.async.wait_group 2;" ::: "memory")

// mma.sync m16n8k16 row.col f32.bf16.bf16.f32 (compute_103-portable HMMA path)
#define MMA16816(c, a, b) asm volatile( \
    "mma.sync.aligned.m16n8k16.row.col.f32.bf16.bf16.f32 " \
    "{%0,%1,%2,%3}, {%4,%5,%6,%7}, {%8,%9}, {%0,%1,%2,%3};" \
    : "+f"((c)[0]), "+f"((c)[1]), "+f"((c)[2]), "+f"((c)[3]) \
    : "r"((a)[0]), "r"((a)[1]), "r"((a)[2]), "r"((a)[3]), "r"((b)[0]), "r"((b)[1]))

// ---------------------------------------------------------------------------
// Prep: split pro into bf16 hi/lo
// ---------------------------------------------------------------------------
__global__ void prep_pro(const float* __restrict__ pro) {
    int i = blockIdx.x * 256 + threadIdx.x;
    if (i >= N_INST * HDIM) return;
    bfsplit(pro[i], g_proh[i], g_prol[i]);
}

// Prep: transpose f32 src(K x N) -> hi/lo bf16 dst(N x K). K,N multiples of 32.
__global__ void __launch_bounds__(256)
prep_trans(const float* __restrict__ src, __nv_bfloat16* __restrict__ dh,
           __nv_bfloat16* __restrict__ dl, int K, int N) {
    __shared__ float t[32][33];
    const int kb = blockIdx.y * 32, nb = blockIdx.x * 32;
    const int tx = threadIdx.x & 31, ty = threadIdx.x >> 5;   // 32 x 8
#pragma unroll
    for (int j = 0; j < 32; j += 8)
        t[ty + j][tx] = src[(size_t)(kb + ty + j) * N + nb + tx];
    __syncthreads();
#pragma unroll
    for (int j = 0; j < 32; j += 8) {
        float x = t[tx][ty + j];
        size_t o = (size_t)(nb + ty + j) * K + kb + tx;
        bfsplit(x, dh[o], dl[o]);
    }
}

// ---------------------------------------------------------------------------
// bf16 mma.sync GEMM, 3-pass hi/lo: C = Ah@Bh^T + Ah@Bl^T + Al@Bh^T (+bias)
// A*: (MPAD x lda) K-major rows. B*: (Ntot x ldb) K-major rows (row = out col).
// 128x128x32 CTA tile, 8 warps (2x4) x (64x32) warp tile, 4-stage cp.async.
// Split-K via blockIdx.z: kOff = z*kLen, C += z*zStride.
// ---------------------------------------------------------------------------
#define LDT   40                      // smem row stride in bf16 (80B: 16B-aligned, conflict-free)
#define TILEB (128 * LDT * 2)         // 10240 B per tile
#define STGB  (2 * TILEB)             // A + B per stage
#define NSTG  4
#define GM_SMEM (NSTG * STGB)         // 81920 B

__global__ void __launch_bounds__(256, 2)
gemm_mma(const __nv_bfloat16* __restrict__ Ah, const __nv_bfloat16* __restrict__ Al, int lda,
         const __nv_bfloat16* __restrict__ Bh, const __nv_bfloat16* __restrict__ Bl, int ldb,
         float* __restrict__ C, int ldc, size_t zStride, int kLen,
         const float* __restrict__ bias)
{
    extern __shared__ char sm[];
    const uint32_t sb = smem_u32(sm);
    const int tid = threadIdx.x;
    const int wid = tid >> 5, lane = tid & 31;
    const int lg = lane >> 2, tg = lane & 3;      // group / thread-in-group
    const int wm = wid & 1, wn = wid >> 1;        // 2 x 4 warp grid
    const int mBase = blockIdx.y * 128, nBase = blockIdx.x * 128;
    const int kOff = blockIdx.z * kLen;
    C += (size_t)blockIdx.z * zStride;

    const int nCh = kLen >> 5;                    // 32-wide K chunks
    const int T = 3 * nCh;

    // loader state: row/k8 handled per thread, cursor over (pass, chunk)
    const int lrow = tid >> 2, lk8 = (tid & 3);   // thread loads rows lrow (A) & lrow (B), 2 chunks... 
    // each thread issues 2 A + 2 B cp.asyncs: indices tid and tid+256
    int lp = 0, lc = 0;

    auto issue = [&](int slot) {
        const __nv_bfloat16* A = (lp < 2) ? Ah : Al;
        const __nv_bfloat16* B = (lp == 1) ? Bl : Bh;
        const int kpos = kOff + lc * 32;
        const uint32_t stg = sb + slot * STGB;
#pragma unroll
        for (int j = 0; j < 2; j++) {
            int idx = tid + 256 * j;
            int row = idx >> 2, k8 = idx & 3;
            const __nv_bfloat16* sa = A + (size_t)(mBase + row) * lda + kpos + k8 * 8;
            const __nv_bfloat16* sbp = B + (size_t)(nBase + row) * ldb + kpos + k8 * 8;
            CP16(stg + row * 80 + k8 * 16, sa);
            CP16(stg + TILEB + row * 80 + k8 * 16, sbp);
        }
        if (++lc == nCh) { lc = 0; ++lp; }
    };
    (void)lrow; (void)lk8;

    float acc[4][4][4];
#pragma unroll
    for (int i = 0; i < 4; i++)
#pragma unroll
        for (int j = 0; j < 4; j++)
#pragma unroll
            for (int k = 0; k < 4; k++) acc[i][j][k] = 0.f;

    // prologue: fill NSTG-1 stages
#pragma unroll
    for (int s = 0; s < NSTG - 1; s++) {
        if (lp < 3) issue(s);
        CP_COMMIT();
    }

    for (int g = 0; g < T; g++) {
        CP_WAIT2();
        __syncthreads();
        if (lp < 3) issue((g + NSTG - 1) & (NSTG - 1));
        CP_COMMIT();

        const char* stg = sm + (g & (NSTG - 1)) * STGB;
        const char* aT = stg;
        const char* bT = stg + TILEB;
#pragma unroll
        for (int ks = 0; ks < 2; ks++) {
            uint32_t af[4][4], bf_[4][2];
#pragma unroll
            for (int mf = 0; mf < 4; mf++) {
                const char* p = aT + (wm * 64 + mf * 16 + lg) * 80 + ks * 32 + tg * 4;
                af[mf][0] = *(const uint32_t*)p;
                af[mf][1] = *(const uint32_t*)(p + 640);   // row +8
                af[mf][2] = *(const uint32_t*)(p + 16);    // k +8
                af[mf][3] = *(const uint32_t*)(p + 656);
            }
#pragma unroll
            for (int nf = 0; nf < 4; nf++) {
                const char* q = bT + (wn * 32 + nf * 8 + lg) * 80 + ks * 32 + tg * 4;
                bf_[nf][0] = *(const uint32_t*)q;
                bf_[nf][1] = *(const uint32_t*)(q + 16);   // k +8
            }
#pragma unroll
            for (int mf = 0; mf < 4; mf++)
#pragma unroll
                for (int nf = 0; nf < 4; nf++)
                    MMA16816(acc[mf][nf], af[mf], bf_[nf]);
        }
    }

    // epilogue: d0,d1 = (row lg, col 2tg / 2tg+1); d2,d3 = (row lg+8, same cols)
#pragma unroll
    for (int mf = 0; mf < 4; mf++) {
        int r0 = mBase + wm * 64 + mf * 16 + lg;
        int r1 = r0 + 8;
#pragma unroll
        for (int nf = 0; nf < 4; nf++) {
            int col = nBase + wn * 32 + nf * 8 + 2 * tg;
            float b0 = 0.f, b1 = 0.f;
            if (bias) { b0 = bias[col]; b1 = bias[col + 1]; }
            float2 v0 = make_float2(acc[mf][nf][0] + b0, acc[mf][nf][1] + b1);
            float2 v1 = make_float2(acc[mf][nf][2] + b0, acc[mf][nf][3] + b1);
            *(float2*)&C[(size_t)r0 * ldc + col] = v0;
            *(float2*)&C[(size_t)r1 * ldc + col] = v1;
        }
    }
}

// ---------------------------------------------------------------------------
// Fused per-instance dynamic conv (proven round-3 math; emits f2 bf16 hi/lo)
// ---------------------------------------------------------------------------
#define SF_LD 264
#define DC_SF_FLOATS (RDIM * SF_LD)
#define DC_SP_FLOATS (HDIM * DDIM)
#define DC_SX_FLOATS (RDIM * DDIM)
#define DC_SMEM_BYTES ((DC_SF_FLOATS + DC_SP_FLOATS + DC_SX_FLOATS) * 4)

__global__ void __launch_bounds__(256)
dynconv_kernel(const float* __restrict__ roi,
               const float* __restrict__ g1, const float* __restrict__ b1,
               const float* __restrict__ g2, const float* __restrict__ b2)
{
    extern __shared__ float sh[];
    float* sF = sh;
    float* sP = sh + DC_SF_FLOATS;
    float* sX = sh + DC_SF_FLOATS + DC_SP_FLOATS;

    const int n = blockIdx.x;
    const int tid = threadIdx.x;
    const int lane = tid & 31;
    const int warp = tid >> 5;

    {
        const float4* prow = (const float4*)(g_params + (size_t)n * PARAMS_PER);
#pragma unroll 1
        for (int i = tid; i < RDIM * 64; i += 256) {
            int r = i >> 6, c4 = i & 63;
            const float4* src = (const float4*)(roi + ((size_t)r * N_INST + n) * HDIM);
            ((float4*)(sF + r * SF_LD))[c4] = src[c4];
        }
#pragma unroll 1
        for (int i = tid; i < DC_SP_FLOATS / 4; i += 256)
            ((float4*)sP)[i] = prow[i];
    }
    __syncthreads();

    {   // bmm1
        const int d0 = (tid & 7) * 8;
        const int r1 = tid >> 3, r2 = r1 + 32;
        const bool has2 = (r2 < RDIM);
        float a1c[8] = {0,0,0,0,0,0,0,0};
        float a2c[8] = {0,0,0,0,0,0,0,0};
#pragma unroll 4
        for (int h = 0; h < HDIM; h++) {
            float4 b0 = *(float4*)&sP[h * DDIM + d0];
            float4 b1v = *(float4*)&sP[h * DDIM + d0 + 4];
            float a1 = sF[r1 * SF_LD + h];
            float a2 = has2 ? sF[r2 * SF_LD + h] : 0.f;
            a1c[0] = fmaf(a1, b0.x, a1c[0]); a1c[1] = fmaf(a1, b0.y, a1c[1]);
            a1c[2] = fmaf(a1, b0.z, a1c[2]); a1c[3] = fmaf(a1, b0.w, a1c[3]);
            a1c[4] = fmaf(a1, b1v.x, a1c[4]); a1c[5] = fmaf(a1, b1v.y, a1c[5]);
            a1c[6] = fmaf(a1, b1v.z, a1c[6]); a1c[7] = fmaf(a1, b1v.w, a1c[7]);
            a2c[0] = fmaf(a2, b0.x, a2c[0]); a2c[1] = fmaf(a2, b0.y, a2c[1]);
            a2c[2] = fmaf(a2, b0.z, a2c[2]); a2c[3] = fmaf(a2, b0.w, a2c[3]);
            a2c[4] = fmaf(a2, b1v.x, a2c[4]); a2c[5] = fmaf(a2, b1v.y, a2c[5]);
            a2c[6] = fmaf(a2, b1v.z, a2c[6]); a2c[7] = fmaf(a2, b1v.w, a2c[7]);
        }
        *(float4*)&sX[r1 * DDIM + d0]     = make_float4(a1c[0], a1c[1], a1c[2], a1c[3]);
        *(float4*)&sX[r1 * DDIM + d0 + 4] = make_float4(a1c[4], a1c[5], a1c[6], a1c[7]);
        if (has2) {
            *(float4*)&sX[r2 * DDIM + d0]     = make_float4(a2c[0], a2c[1], a2c[2], a2c[3]);
            *(float4*)&sX[r2 * DDIM + d0 + 4] = make_float4(a2c[4], a2c[5], a2c[6], a2c[7]);
        }
    }
    __syncthreads();

    {   // load p2
        const float4* prow = (const float4*)(g_params + (size_t)n * PARAMS_PER + HDIM * DDIM);
#pragma unroll 1
        for (int i = tid; i < DC_SP_FLOATS / 4; i += 256)
            ((float4*)sP)[i] = prow[i];
    }

    {   // LN over D + relu
        float gg0 = g1[lane], gg1 = g1[lane + 32];
        float bb0 = b1[lane], bb1 = b1[lane + 32];
        for (int r = warp; r < RDIM; r += 8) {
            float v0 = sX[r * DDIM + lane];
            float v1 = sX[r * DDIM + lane + 32];
            float s = warp_sum(v0 + v1);
            float sq = warp_sum(v0 * v0 + v1 * v1);
            float m = s * (1.f / DDIM);
            float var = sq * (1.f / DDIM) - m * m;
            float inv = rsqrtf(var + 1e-5f);
            sX[r * DDIM + lane]      = fmaxf((v0 - m) * inv * gg0 + bb0, 0.f);
            sX[r * DDIM + lane + 32] = fmaxf((v1 - m) * inv * gg1 + bb1, 0.f);
        }
    }
    __syncthreads();

    {   // bmm2 -> sF
        const int h0 = (tid & 31) * 8;
        const int rb = tid >> 5;
#pragma unroll 1
        for (int p = 0; p < 4; p++) {
            int r1 = rb + 16 * p;
            if (r1 >= RDIM) break;
            int r2 = r1 + 8;
            bool has2 = (r2 < RDIM);
            float a1c[8] = {0,0,0,0,0,0,0,0};
            float a2c[8] = {0,0,0,0,0,0,0,0};
#pragma unroll 4
            for (int k = 0; k < DDIM; k++) {
                float4 b0 = *(float4*)&sP[k * HDIM + h0];
                float4 b1v = *(float4*)&sP[k * HDIM + h0 + 4];
                float a1 = sX[r1 * DDIM + k];
                float a2 = has2 ? sX[r2 * DDIM + k] : 0.f;
                a1c[0] = fmaf(a1, b0.x, a1c[0]); a1c[1] = fmaf(a1, b0.y, a1c[1]);
                a1c[2] = fmaf(a1, b0.z, a1c[2]); a1c[3] = fmaf(a1, b0.w, a1c[3]);
                a1c[4] = fmaf(a1, b1v.x, a1c[4]); a1c[5] = fmaf(a1, b1v.y, a1c[5]);
                a1c[6] = fmaf(a1, b1v.z, a1c[6]); a1c[7] = fmaf(a1, b1v.w, a1c[7]);
                a2c[0] = fmaf(a2, b0.x, a2c[0]); a2c[1] = fmaf(a2, b0.y, a2c[1]);
                a2c[2] = fmaf(a2, b0.z, a2c[2]); a2c[3] = fmaf(a2, b0.w, a2c[3]);
                a2c[4] = fmaf(a2, b1v.x, a2c[4]); a2c[5] = fmaf(a2, b1v.y, a2c[5]);
                a2c[6] = fmaf(a2, b1v.z, a2c[6]); a2c[7] = fmaf(a2, b1v.w, a2c[7]);
            }
#pragma unroll
            for (int j = 0; j < 8; j++) sF[r1 * SF_LD + h0 + j] = a1c[j];
            if (has2) {
#pragma unroll
                for (int j = 0; j < 8; j++) sF[r2 * SF_LD + h0 + j] = a2c[j];
            }
        }
    }
    __syncthreads();

    {   // LN over H + relu -> g_f2h/g_f2l (bf16 hi/lo)
        float gA[8], bA[8];
#pragma unroll
        for (int j = 0; j < 8; j++) { gA[j] = g2[lane + 32 * j]; bA[j] = b2[lane + 32 * j]; }
        __nv_bfloat16* dh = g_f2h + (size_t)n * F2_COLS;
        __nv_bfloat16* dl = g_f2l + (size_t)n * F2_COLS;
        for (int r = warp; r < RDIM; r += 8) {
            float v[8];
            float s = 0.f, sq = 0.f;
#pragma unroll
            for (int j = 0; j < 8; j++) {
                v[j] = sF[r * SF_LD + lane + 32 * j];
                s += v[j]; sq += v[j] * v[j];
            }
            s = warp_sum(s); sq = warp_sum(sq);
            float m = s * (1.f / HDIM);
            float var = sq * (1.f / HDIM) - m * m;
            float inv = rsqrtf(var + 1e-5f);
#pragma unroll
            for (int j = 0; j < 8; j++) {
                int h = lane + 32 * j;
                float o = fmaxf((v[j] - m) * inv * gA[j] + bA[j], 0.f);
                bfsplit(o, dh[r * HDIM + h], dl[r * HDIM + h]);
            }
        }
    }
}

// ---------------------------------------------------------------------------
// Reduce split-K partials + bias, LN over H + relu -> out (2000 x 256)
// ---------------------------------------------------------------------------
__global__ void __launch_bounds__(256)
reduce_ln3(const float* __restrict__ b_out,
           const float* __restrict__ g3, const float* __restrict__ b3,
           float* __restrict__ out)
{
    const int lane = threadIdx.x & 31;
    const int warp = threadIdx.x >> 5;
    const int row = blockIdx.x * 8 + warp;
    float v[8];
    float s = 0.f, sq = 0.f;
#pragma unroll
    for (int j = 0; j < 8; j++) {
        int h = lane + 32 * j;
        float a = b_out[h];
#pragma unroll
        for (int z = 0; z < KSPL; z++)
            a += g_kpart[((size_t)z * MPAD + row) * HDIM + h];
        v[j] = a; s += a; sq += a * a;
    }
    s = warp_sum(s); sq = warp_sum(sq);
    float m = s * (1.f / HDIM);
    float var = sq * (1.f / HDIM) - m * m;
    float inv = rsqrtf(var + 1e-5f);
#pragma unroll
    for (int j = 0; j < 8; j++) {
        int h = lane + 32 * j;
        float o = (v[j] - m) * inv * g3[h] + b3[h];
        out[(size_t)row * HDIM + h] = fmaxf(o, 0.f);
    }
}

// ---------------------------------------------------------------------------
extern "C" void kernel_launch(void* const* d_in, const int* in_sizes, int n_in,
                              void* d_out, int out_size)
{
    (void)in_sizes; (void)n_in; (void)out_size;
    const float* pro   = (const float*)d_in[0];
    const float* roi   = (const float*)d_in[1];
    const float* W_dyn = (const float*)d_in[2];
    const float* b_dyn = (const float*)d_in[3];
    const float* W_out = (const float*)d_in[4];
    const float* b_out = (const float*)d_in[5];
    const float* g1 = (const float*)d_in[6];
    const float* b1 = (const float*)d_in[7];
    const float* g2 = (const float*)d_in[8];
    const float* b2 = (const float*)d_in[9];
    const float* g3 = (const float*)d_in[10];
    const float* b3 = (const float*)d_in[11];
    float* out = (float*)d_out;

    float *p_params = nullptr, *p_kpart = nullptr;
    __nv_bfloat16 *p_proh, *p_prol, *p_wdh, *p_wdl, *p_woh, *p_wol, *p_f2h, *p_f2l;
    cudaGetSymbolAddress((void**)&p_params, g_params);
    cudaGetSymbolAddress((void**)&p_kpart, g_kpart);
    cudaGetSymbolAddress((void**)&p_proh, g_proh);
    cudaGetSymbolAddress((void**)&p_prol, g_prol);
    cudaGetSymbolAddress((void**)&p_wdh, g_wdh);
    cudaGetSymbolAddress((void**)&p_wdl, g_wdl);
    cudaGetSymbolAddress((void**)&p_woh, g_woh);
    cudaGetSymbolAddress((void**)&p_wol, g_wol);
    cudaGetSymbolAddress((void**)&p_f2h, g_f2h);
    cudaGetSymbolAddress((void**)&p_f2l, g_f2l);

    cudaFuncSetAttribute(dynconv_kernel,
                         cudaFuncAttributeMaxDynamicSharedMemorySize, DC_SMEM_BYTES);
    cudaFuncSetAttribute(gemm_mma,
                         cudaFuncAttributeMaxDynamicSharedMemorySize, GM_SMEM);

    // P0: hi/lo splits + K-major transposes
    prep_pro<<<(N_INST * HDIM + 255) / 256, 256>>>(pro);
    prep_trans<<<dim3(PARAMS_PER / 32, HDIM / 32), 256>>>(W_dyn, p_wdh, p_wdl, HDIM, PARAMS_PER);
    prep_trans<<<dim3(HDIM / 32, F2_COLS / 32), 256>>>(W_out, p_woh, p_wol, F2_COLS, HDIM);

    // K1: params = pro @ W_dyn + b_dyn   (mma.sync bf16, 3-pass)
    gemm_mma<<<dim3(PARAMS_PER / 128, MPAD / 128, 1), 256, GM_SMEM>>>(
        p_proh, p_prol, HDIM, p_wdh, p_wdl, HDIM,
        p_params, PARAMS_PER, 0, HDIM, b_dyn);

    // K2: fused dynamic conv -> f2 hi/lo
    dynconv_kernel<<<N_INST, 256, DC_SMEM_BYTES>>>(roi, g1, b1, g2, b2);

    // K3: partials of F2 @ W_out, split-K=14 (mma.sync bf16, 3-pass)
    gemm_mma<<<dim3(HDIM / 128, MPAD / 128, KSPL), 256, GM_SMEM>>>(
        p_f2h, p_f2l, F2_COLS, p_woh, p_wol, F2_COLS,
        p_kpart, HDIM, (size_t)MPAD * HDIM, KPERZ, nullptr);

    // K4: reduce + bias + LN + relu -> out
    reduce_ln3<<<N_INST / 8, 256>>>(b_out, g3, b3, out);
}

// round 9
// speedup vs baseline: 1.7929x; 1.3726x over previous
#include <cuda_runtime.h>
#include <cuda_bf16.h>
#include <cstdint>
#include <cstddef>

#define N_INST 2000
#define MPAD   2048
#define HDIM   256
#define DDIM   64
#define RDIM   49
#define PARAMS_PER 32768
#define F2_COLS 12544
#define KSPL 14
#define KPERZ (F2_COLS / KSPL)   // 896

// Scratch: __device__ globals (zero-initialized; bf16 A rows [2000,2048) stay 0)
__device__ __align__(256) float g_params[(size_t)MPAD * PARAMS_PER];
__device__ __align__(256) __nv_bfloat16 g_proh[MPAD * HDIM];
__device__ __align__(256) __nv_bfloat16 g_prol[MPAD * HDIM];
__device__ __align__(256) __nv_bfloat16 g_wdh[(size_t)PARAMS_PER * HDIM];
__device__ __align__(256) __nv_bfloat16 g_wdl[(size_t)PARAMS_PER * HDIM];
__device__ __align__(256) __nv_bfloat16 g_woh[(size_t)HDIM * F2_COLS];
__device__ __align__(256) __nv_bfloat16 g_wol[(size_t)HDIM * F2_COLS];
__device__ __align__(256) __nv_bfloat16 g_f2h[(size_t)MPAD * F2_COLS];
__device__ __align__(256) __nv_bfloat16 g_f2l[(size_t)MPAD * F2_COLS];
__device__ __align__(256) float g_kpart[(size_t)KSPL * MPAD * HDIM];

// ---------------- small helpers ----------------
__device__ __forceinline__ float warp_sum(float v) {
#pragma unroll
    for (int o = 16; o > 0; o >>= 1) v += __shfl_xor_sync(0xffffffffu, v, o);
    return v;
}
__device__ __forceinline__ void bfsplit(float x, __nv_bfloat16& h, __nv_bfloat16& l) {
    h = __float2bfloat16(x);
    l = __float2bfloat16(x - __bfloat162float(h));
}
__device__ __forceinline__ uint32_t smem_u32(const void* p) {
    uint32_t a;
    asm("{ .reg .u64 t; cvta.to.shared.u64 t, %1; cvt.u32.u64 %0, t; }" : "=r"(a) : "l"(p));
    return a;
}
__device__ __forceinline__ double dup2(float a) {
    double d; asm("mov.b64 %0, {%1, %1};" : "=d"(d) : "f"(a)); return d;
}
__device__ __forceinline__ void fma2(double& c, double a, double b) {
    asm("fma.rn.f32x2 %0, %1, %2, %0;" : "+d"(c) : "d"(a), "d"(b));
}
__device__ __forceinline__ float2 upk2(double v) {
    float2 r; asm("mov.b64 {%0, %1}, %2;" : "=f"(r.x), "=f"(r.y) : "d"(v)); return r;
}
#define CP16(dst, src) asm volatile( \
    "cp.async.cg.shared.global [%0], [%1], 16;" :: "r"(dst), "l"(src) : "memory")
#define CP_COMMIT() asm volatile("cp.async.commit_group;" ::: "memory")
#define CP_WAIT2()  asm volatile("cp.async.wait_group 2;" ::: "memory")

#define MMA16816(c, a, b) asm volatile( \
    "mma.sync.aligned.m16n8k16.row.col.f32.bf16.bf16.f32 " \
    "{%0,%1,%2,%3}, {%4,%5,%6,%7}, {%8,%9}, {%0,%1,%2,%3};" \
    : "+f"((c)[0]), "+f"((c)[1]), "+f"((c)[2]), "+f"((c)[3]) \
    : "r"((a)[0]), "r"((a)[1]), "r"((a)[2]), "r"((a)[3]), "r"((b)[0]), "r"((b)[1]))

#define LDMX4(r0, r1, r2, r3, addr) asm volatile( \
    "ldmatrix.sync.aligned.m8n8.x4.shared.b16 {%0,%1,%2,%3}, [%4];" \
    : "=r"(r0), "=r"(r1), "=r"(r2), "=r"(r3) : "r"(addr))

// ---------------------------------------------------------------------------
// Prep kernels
// ---------------------------------------------------------------------------
__global__ void prep_pro(const float* __restrict__ pro) {
    int i = blockIdx.x * 256 + threadIdx.x;
    if (i >= N_INST * HDIM) return;
    bfsplit(pro[i], g_proh[i], g_prol[i]);
}

__global__ void __launch_bounds__(256)
prep_trans(const float* __restrict__ src, __nv_bfloat16* __restrict__ dh,
           __nv_bfloat16* __restrict__ dl, int K, int N) {
    __shared__ float t[32][33];
    const int kb = blockIdx.y * 32, nb = blockIdx.x * 32;
    const int tx = threadIdx.x & 31, ty = threadIdx.x >> 5;
#pragma unroll
    for (int j = 0; j < 32; j += 8)
        t[ty + j][tx] = src[(size_t)(kb + ty + j) * N + nb + tx];
    __syncthreads();
#pragma unroll
    for (int j = 0; j < 32; j += 8) {
        float x = t[tx][ty + j];
        size_t o = (size_t)(nb + ty + j) * K + kb + tx;
        bfsplit(x, dh[o], dl[o]);
    }
}

// ---------------------------------------------------------------------------
// bf16 mma.sync GEMM, 3-pass hi/lo, ldmatrix fragment loads.
// 128x128x32 CTA tile, 8 warps (2x4), 4-stage cp.async, split-K via z.
// ---------------------------------------------------------------------------
#define LDT   40
#define TILEB (128 * LDT * 2)         // 10240 B
#define STGB  (2 * TILEB)
#define NSTG  4
#define GM_SMEM (NSTG * STGB)         // 81920 B

__global__ void __launch_bounds__(256, 2)
gemm_mma(const __nv_bfloat16* __restrict__ Ah, const __nv_bfloat16* __restrict__ Al, int lda,
         const __nv_bfloat16* __restrict__ Bh, const __nv_bfloat16* __restrict__ Bl, int ldb,
         float* __restrict__ C, int ldc, size_t zStride, int kLen,
         const float* __restrict__ bias)
{
    extern __shared__ char sm[];
    const uint32_t sb = smem_u32(sm);
    const int tid = threadIdx.x;
    const int wid = tid >> 5, lane = tid & 31;
    const int lg = lane >> 2, tg = lane & 3;
    const int wm = wid & 1, wn = wid >> 1;
    const int mBase = blockIdx.y * 128, nBase = blockIdx.x * 128;
    const int kOff = blockIdx.z * kLen;
    C += (size_t)blockIdx.z * zStride;

    const int nCh = kLen >> 5;
    const int T = 3 * nCh;

    int lp = 0, lc = 0;
    auto issue = [&](int slot) {
        const __nv_bfloat16* A = (lp < 2) ? Ah : Al;
        const __nv_bfloat16* B = (lp == 1) ? Bl : Bh;
        const int kpos = kOff + lc * 32;
        const uint32_t stg = sb + slot * STGB;
#pragma unroll
        for (int j = 0; j < 2; j++) {
            int idx = tid + 256 * j;
            int row = idx >> 2, k8 = idx & 3;
            const __nv_bfloat16* sa = A + (size_t)(mBase + row) * lda + kpos + k8 * 8;
            const __nv_bfloat16* sbp = B + (size_t)(nBase + row) * ldb + kpos + k8 * 8;
            CP16(stg + row * 80 + k8 * 16, sa);
            CP16(stg + TILEB + row * 80 + k8 * 16, sbp);
        }
        if (++lc == nCh) { lc = 0; ++lp; }
    };

    // ldmatrix lane-address selectors (canonical m16n8k16 fragment order)
    const uint32_t aSel = (uint32_t)(wm * 64 + (lane & 7) + ((lane >> 3) & 1) * 8) * 80
                        + ((lane >> 4) & 1) * 16;
    const uint32_t bSel = (uint32_t)(wn * 32 + (lane & 7) + ((lane >> 4) & 1) * 8) * 80
                        + ((lane >> 3) & 1) * 16;

    float acc[4][4][4];
#pragma unroll
    for (int i = 0; i < 4; i++)
#pragma unroll
        for (int j = 0; j < 4; j++)
#pragma unroll
            for (int k = 0; k < 4; k++) acc[i][j][k] = 0.f;

#pragma unroll
    for (int s = 0; s < NSTG - 1; s++) {
        if (lp < 3) issue(s);
        CP_COMMIT();
    }

    for (int g = 0; g < T; g++) {
        CP_WAIT2();
        __syncthreads();
        if (lp < 3) issue((g + NSTG - 1) & (NSTG - 1));
        CP_COMMIT();

        const uint32_t stgu = sb + (g & (NSTG - 1)) * STGB;
#pragma unroll
        for (int ks = 0; ks < 2; ks++) {
            uint32_t af[4][4], bfr[4][2];
#pragma unroll
            for (int mf = 0; mf < 4; mf++) {
                uint32_t addr = stgu + aSel + mf * (16 * 80) + ks * 32;
                LDMX4(af[mf][0], af[mf][1], af[mf][2], af[mf][3], addr);
            }
#pragma unroll
            for (int nfp = 0; nfp < 2; nfp++) {
                uint32_t addr = stgu + TILEB + bSel + nfp * (16 * 80) + ks * 32;
                LDMX4(bfr[2 * nfp][0], bfr[2 * nfp][1],
                      bfr[2 * nfp + 1][0], bfr[2 * nfp + 1][1], addr);
            }
#pragma unroll
            for (int mf = 0; mf < 4; mf++)
#pragma unroll
                for (int nf = 0; nf < 4; nf++)
                    MMA16816(acc[mf][nf], af[mf], bfr[nf]);
        }
    }

#pragma unroll
    for (int mf = 0; mf < 4; mf++) {
        int r0 = mBase + wm * 64 + mf * 16 + lg;
        int r1 = r0 + 8;
#pragma unroll
        for (int nf = 0; nf < 4; nf++) {
            int col = nBase + wn * 32 + nf * 8 + 2 * tg;
            float b0 = 0.f, b1 = 0.f;
            if (bias) { b0 = bias[col]; b1 = bias[col + 1]; }
            float2 v0 = make_float2(acc[mf][nf][0] + b0, acc[mf][nf][1] + b1);
            float2 v1 = make_float2(acc[mf][nf][2] + b0, acc[mf][nf][3] + b1);
            *(float2*)&C[(size_t)r0 * ldc + col] = v0;
            *(float2*)&C[(size_t)r1 * ldc + col] = v1;
        }
    }
}

// ---------------------------------------------------------------------------
// Fused dynamic conv: halved staging (98.5 KB smem -> 2 CTA/SM) + f32x2 math.
// ---------------------------------------------------------------------------
#define SF_LD 264
#define DC_SP (RDIM * SF_LD)              // 12936 floats: sF
#define DC_SX (DC_SP + 8192)              // sP = 8192 floats (32KB half)
#define DC_TOT (DC_SX + 64 * DDIM)        // sX padded to 64 rows
#define DC_SMEM_BYTES (DC_TOT * 4)        // 100,896 B

__global__ void __launch_bounds__(256, 2)
dynconv_kernel(const float* __restrict__ roi,
               const float* __restrict__ g1, const float* __restrict__ b1,
               const float* __restrict__ g2, const float* __restrict__ b2)
{
    extern __shared__ float sh[];
    float* sF = sh;
    float* sP = sh + DC_SP;
    float* sX = sh + DC_SX;

    const int n = blockIdx.x;
    const int tid = threadIdx.x;
    const int lane = tid & 31;
    const int warp = tid >> 5;
    const float4* prow = (const float4*)(g_params + (size_t)n * PARAMS_PER);

    // ---- load feats (49 x 256) + p1 half0 (h 0..127) ----
#pragma unroll 1
    for (int i = tid; i < RDIM * 64; i += 256) {
        int r = i >> 6, c4 = i & 63;
        const float4* src = (const float4*)(roi + ((size_t)r * N_INST + n) * HDIM);
        ((float4*)(sF + r * SF_LD))[c4] = src[c4];
    }
#pragma unroll 1
    for (int i = tid; i < 2048; i += 256) ((float4*)sP)[i] = prow[i];
    __syncthreads();

    // ---- bmm1: f1[r][d] = sum_h feats[r][h] * p1[h][d]  (f32x2, h-halves) ----
    {
        const int d0 = (tid & 7) * 8;
        const int r1 = tid >> 3, r2 = r1 + 32;
        const bool has2 = (r2 < RDIM);
        double a1c[4] = {0, 0, 0, 0}, a2c[4] = {0, 0, 0, 0};
#pragma unroll 1
        for (int hb = 0; hb < 2; hb++) {
            if (hb) {
                __syncthreads();
#pragma unroll 1
                for (int i = tid; i < 2048; i += 256) ((float4*)sP)[i] = prow[2048 + i];
                __syncthreads();
            }
            const int hBase = hb * 128;
#pragma unroll 4
            for (int hh = 0; hh < 128; hh++) {
                double2 b01 = *(const double2*)&sP[hh * DDIM + d0];
                double2 b23 = *(const double2*)&sP[hh * DDIM + d0 + 4];
                double a1 = dup2(sF[r1 * SF_LD + hBase + hh]);
                fma2(a1c[0], a1, b01.x); fma2(a1c[1], a1, b01.y);
                fma2(a1c[2], a1, b23.x); fma2(a1c[3], a1, b23.y);
                double a2 = dup2(has2 ? sF[r2 * SF_LD + hBase + hh] : 0.f);
                fma2(a2c[0], a2, b01.x); fma2(a2c[1], a2, b01.y);
                fma2(a2c[2], a2, b23.x); fma2(a2c[3], a2, b23.y);
            }
        }
        float2 u0 = upk2(a1c[0]), u1 = upk2(a1c[1]), u2 = upk2(a1c[2]), u3 = upk2(a1c[3]);
        *(float4*)&sX[r1 * DDIM + d0]     = make_float4(u0.x, u0.y, u1.x, u1.y);
        *(float4*)&sX[r1 * DDIM + d0 + 4] = make_float4(u2.x, u2.y, u3.x, u3.y);
        if (has2) {
            float2 w0 = upk2(a2c[0]), w1 = upk2(a2c[1]), w2 = upk2(a2c[2]), w3 = upk2(a2c[3]);
            *(float4*)&sX[r2 * DDIM + d0]     = make_float4(w0.x, w0.y, w1.x, w1.y);
            *(float4*)&sX[r2 * DDIM + d0 + 4] = make_float4(w2.x, w2.y, w3.x, w3.y);
        }
    }
    __syncthreads();

    // ---- LN over D=64 + relu, in place on sX ----
    {
        float gg0 = g1[lane], gg1 = g1[lane + 32];
        float bb0 = b1[lane], bb1 = b1[lane + 32];
        for (int r = warp; r < RDIM; r += 8) {
            float v0 = sX[r * DDIM + lane];
            float v1 = sX[r * DDIM + lane + 32];
            float s = warp_sum(v0 + v1);
            float sq = warp_sum(v0 * v0 + v1 * v1);
            float m = s * (1.f / DDIM);
            float var = sq * (1.f / DDIM) - m * m;
            float inv = rsqrtf(var + 1e-5f);
            sX[r * DDIM + lane]      = fmaxf((v0 - m) * inv * gg0 + bb0, 0.f);
            sX[r * DDIM + lane + 32] = fmaxf((v1 - m) * inv * gg1 + bb1, 0.f);
        }
    }

    // ---- bmm2: f2[r][h] = sum_d f1[r][d] * p2[d][h]  (f32x2, h-halves) ----
    {
        const int h0l = (tid & 15) * 8;       // local col 0..120
        const int rb2 = tid >> 4;             // 0..15
        const float4* p2 = (const float4*)(g_params + (size_t)n * PARAMS_PER + HDIM * DDIM);
#pragma unroll 1
        for (int hb = 0; hb < 2; hb++) {
            __syncthreads();                  // prior sP readers / sX writers done
#pragma unroll 1
            for (int i = tid; i < 2048; i += 256) {
                int d = i >> 5, c = i & 31;   // p2 row d, 128-col half hb
                ((float4*)sP)[i] = p2[d * 64 + hb * 32 + c];
            }
            __syncthreads();
            double ac[4][4];
#pragma unroll
            for (int j = 0; j < 4; j++)
#pragma unroll
                for (int q = 0; q < 4; q++) ac[j][q] = 0.0;
#pragma unroll 4
            for (int kk = 0; kk < DDIM; kk++) {
                double2 b01 = *(const double2*)&sP[kk * 128 + h0l];
                double2 b23 = *(const double2*)&sP[kk * 128 + h0l + 4];
#pragma unroll
                for (int j = 0; j < 4; j++) {
                    double a = dup2(sX[(rb2 + 16 * j) * DDIM + kk]);
                    fma2(ac[j][0], a, b01.x); fma2(ac[j][1], a, b01.y);
                    fma2(ac[j][2], a, b23.x); fma2(ac[j][3], a, b23.y);
                }
            }
#pragma unroll
            for (int j = 0; j < 4; j++) {
                int row = rb2 + 16 * j;
                if (row < RDIM) {
                    float2 u0 = upk2(ac[j][0]), u1 = upk2(ac[j][1]);
                    float2 u2 = upk2(ac[j][2]), u3 = upk2(ac[j][3]);
                    float* dst = &sF[row * SF_LD + hb * 128 + h0l];
                    *(float4*)(dst)     = make_float4(u0.x, u0.y, u1.x, u1.y);
                    *(float4*)(dst + 4) = make_float4(u2.x, u2.y, u3.x, u3.y);
                }
            }
        }
    }
    __syncthreads();

    // ---- LN over H=256 + relu -> g_f2h/g_f2l (bf16 hi/lo) ----
    {
        float gA[8], bA[8];
#pragma unroll
        for (int j = 0; j < 8; j++) { gA[j] = g2[lane + 32 * j]; bA[j] = b2[lane + 32 * j]; }
        __nv_bfloat16* dh = g_f2h + (size_t)n * F2_COLS;
        __nv_bfloat16* dl = g_f2l + (size_t)n * F2_COLS;
        for (int r = warp; r < RDIM; r += 8) {
            float v[8];
            float s = 0.f, sq = 0.f;
#pragma unroll
            for (int j = 0; j < 8; j++) {
                v[j] = sF[r * SF_LD + lane + 32 * j];
                s += v[j]; sq += v[j] * v[j];
            }
            s = warp_sum(s); sq = warp_sum(sq);
            float m = s * (1.f / HDIM);
            float var = sq * (1.f / HDIM) - m * m;
            float inv = rsqrtf(var + 1e-5f);
#pragma unroll
            for (int j = 0; j < 8; j++) {
                int h = lane + 32 * j;
                float o = fmaxf((v[j] - m) * inv * gA[j] + bA[j], 0.f);
                bfsplit(o, dh[r * HDIM + h], dl[r * HDIM + h]);
            }
        }
    }
}

// ---------------------------------------------------------------------------
// Reduce split-K partials + bias, LN over H + relu -> out (2000 x 256)
// ---------------------------------------------------------------------------
__global__ void __launch_bounds__(256)
reduce_ln3(const float* __restrict__ b_out,
           const float* __restrict__ g3, const float* __restrict__ b3,
           float* __restrict__ out)
{
    const int lane = threadIdx.x & 31;
    const int warp = threadIdx.x >> 5;
    const int row = blockIdx.x * 8 + warp;
    float v[8];
    float s = 0.f, sq = 0.f;
#pragma unroll
    for (int j = 0; j < 8; j++) {
        int h = lane + 32 * j;
        float a = b_out[h];
#pragma unroll
        for (int z = 0; z < KSPL; z++)
            a += g_kpart[((size_t)z * MPAD + row) * HDIM + h];
        v[j] = a; s += a; sq += a * a;
    }
    s = warp_sum(s); sq = warp_sum(sq);
    float m = s * (1.f / HDIM);
    float var = sq * (1.f / HDIM) - m * m;
    float inv = rsqrtf(var + 1e-5f);
#pragma unroll
    for (int j = 0; j < 8; j++) {
        int h = lane + 32 * j;
        float o = (v[j] - m) * inv * g3[h] + b3[h];
        out[(size_t)row * HDIM + h] = fmaxf(o, 0.f);
    }
}

// ---------------------------------------------------------------------------
extern "C" void kernel_launch(void* const* d_in, const int* in_sizes, int n_in,
                              void* d_out, int out_size)
{
    (void)in_sizes; (void)n_in; (void)out_size;
    const float* pro   = (const float*)d_in[0];
    const float* roi   = (const float*)d_in[1];
    const float* W_dyn = (const float*)d_in[2];
    const float* b_dyn = (const float*)d_in[3];
    const float* W_out = (const float*)d_in[4];
    const float* b_out = (const float*)d_in[5];
    const float* g1 = (const float*)d_in[6];
    const float* b1 = (const float*)d_in[7];
    const float* g2 = (const float*)d_in[8];
    const float* b2 = (const float*)d_in[9];
    const float* g3 = (const float*)d_in[10];
    const float* b3 = (const float*)d_in[11];
    float* out = (float*)d_out;

    float *p_params = nullptr, *p_kpart = nullptr;
    __nv_bfloat16 *p_wdh, *p_wdl, *p_woh, *p_wol, *p_proh, *p_prol, *p_f2h, *p_f2l;
    cudaGetSymbolAddress((void**)&p_params, g_params);
    cudaGetSymbolAddress((void**)&p_kpart, g_kpart);
    cudaGetSymbolAddress((void**)&p_proh, g_proh);
    cudaGetSymbolAddress((void**)&p_prol, g_prol);
    cudaGetSymbolAddress((void**)&p_wdh, g_wdh);
    cudaGetSymbolAddress((void**)&p_wdl, g_wdl);
    cudaGetSymbolAddress((void**)&p_woh, g_woh);
    cudaGetSymbolAddress((void**)&p_wol, g_wol);
    cudaGetSymbolAddress((void**)&p_f2h, g_f2h);
    cudaGetSymbolAddress((void**)&p_f2l, g_f2l);

    cudaFuncSetAttribute(dynconv_kernel,
                         cudaFuncAttributeMaxDynamicSharedMemorySize, DC_SMEM_BYTES);
    cudaFuncSetAttribute(gemm_mma,
                         cudaFuncAttributeMaxDynamicSharedMemorySize, GM_SMEM);

    // P0: hi/lo splits + K-major transposes
    prep_pro<<<(N_INST * HDIM + 255) / 256, 256>>>(pro);
    prep_trans<<<dim3(PARAMS_PER / 32, HDIM / 32), 256>>>(W_dyn, p_wdh, p_wdl, HDIM, PARAMS_PER);
    prep_trans<<<dim3(HDIM / 32, F2_COLS / 32), 256>>>(W_out, p_woh, p_wol, F2_COLS, HDIM);

    // K1: params = pro @ W_dyn + b_dyn (mma.sync bf16 3-pass, ldmatrix)
    gemm_mma<<<dim3(PARAMS_PER / 128, MPAD / 128, 1), 256, GM_SMEM>>>(
        p_proh, p_prol, HDIM, p_wdh, p_wdl, HDIM,
        p_params, PARAMS_PER, 0, HDIM, b_dyn);

    // K2: fused dynamic conv -> f2 hi/lo
    dynconv_kernel<<<N_INST, 256, DC_SMEM_BYTES>>>(roi, g1, b1, g2, b2);

    // K3: partials of F2 @ W_out, split-K=14
    gemm_mma<<<dim3(HDIM / 128, MPAD / 128, KSPL), 256, GM_SMEM>>>(
        p_f2h, p_f2l, F2_COLS, p_woh, p_wol, F2_COLS,
        p_kpart, HDIM, (size_t)MPAD * HDIM, KPERZ, nullptr);

    // K4: reduce + bias + LN + relu -> out
    reduce_ln3<<<N_INST / 8, 256>>>(b_out, g3, b3, out);
}

// round 14
// speedup vs baseline: 2.4100x; 1.3442x over previous
#include <cuda_runtime.h>
#include <cuda_bf16.h>
#include <cstdint>
#include <cstddef>

#define N_INST 2000
#define MPAD   2048
#define HDIM   256
#define DDIM   64
#define RDIM   49
#define PARAMS_PER 32768
#define F2_COLS 12544
#define KSPL 14
#define KPERZ (F2_COLS / KSPL)   // 896

// Scratch: __device__ globals (zero-initialized; bf16 A rows [2000,2048) stay 0)
__device__ __align__(256) __nv_bfloat16 g_prmh[(size_t)MPAD * PARAMS_PER]; // params hi
__device__ __align__(256) __nv_bfloat16 g_prml[(size_t)MPAD * PARAMS_PER]; // params lo
__device__ __align__(256) __nv_bfloat16 g_proh[MPAD * HDIM];
__device__ __align__(256) __nv_bfloat16 g_prol[MPAD * HDIM];
__device__ __align__(256) __nv_bfloat16 g_wdh[(size_t)PARAMS_PER * HDIM];
__device__ __align__(256) __nv_bfloat16 g_wdl[(size_t)PARAMS_PER * HDIM];
__device__ __align__(256) __nv_bfloat16 g_woh[(size_t)HDIM * F2_COLS];
__device__ __align__(256) __nv_bfloat16 g_wol[(size_t)HDIM * F2_COLS];
__device__ __align__(256) __nv_bfloat16 g_f2h[(size_t)MPAD * F2_COLS];
__device__ __align__(256) __nv_bfloat16 g_f2l[(size_t)MPAD * F2_COLS];
__device__ __align__(256) float g_kpart[(size_t)KSPL * MPAD * HDIM];

// ---------------- small helpers ----------------
__device__ __forceinline__ float warp_sum(float v) {
#pragma unroll
    for (int o = 16; o > 0; o >>= 1) v += __shfl_xor_sync(0xffffffffu, v, o);
    return v;
}
__device__ __forceinline__ void bfsplit(float x, __nv_bfloat16& h, __nv_bfloat16& l) {
    h = __float2bfloat16(x);
    l = __float2bfloat16(x - __bfloat162float(h));
}
__device__ __forceinline__ uint32_t smem_u32(const void* p) {
    uint32_t a;
    asm("{ .reg .u64 t; cvta.to.shared.u64 t, %1; cvt.u32.u64 %0, t; }" : "=r"(a) : "l"(p));
    return a;
}
#define CP16(dst, src) asm volatile( \
    "cp.async.cg.shared.global [%0], [%1], 16;" :: "r"(dst), "l"(src) : "memory")
#define CP_COMMIT() asm volatile("cp.async.commit_group;" ::: "memory")
#define CP_WAIT2()  asm volatile("cp.async.wait_group 2;" ::: "memory")

#define MMA16816(c, a, b) asm volatile( \
    "mma.sync.aligned.m16n8k16.row.col.f32.bf16.bf16.f32 " \
    "{%0,%1,%2,%3}, {%4,%5,%6,%7}, {%8,%9}, {%0,%1,%2,%3};" \
    : "+f"((c)[0]), "+f"((c)[1]), "+f"((c)[2]), "+f"((c)[3]) \
    : "r"((a)[0]), "r"((a)[1]), "r"((a)[2]), "r"((a)[3]), "r"((b)[0]), "r"((b)[1]))

#define LDMX4(r0, r1, r2, r3, addr) asm volatile( \
    "ldmatrix.sync.aligned.m8n8.x4.shared.b16 {%0,%1,%2,%3}, [%4];" \
    : "=r"(r0), "=r"(r1), "=r"(r2), "=r"(r3) : "r"(addr))
#define LDMX4T(r0, r1, r2, r3, addr) asm volatile( \
    "ldmatrix.sync.aligned.m8n8.x4.trans.shared.b16 {%0,%1,%2,%3}, [%4];" \
    : "=r"(r0), "=r"(r1), "=r"(r2), "=r"(r3) : "r"(addr))

// ---------------------------------------------------------------------------
// Prep kernels
// ---------------------------------------------------------------------------
__global__ void prep_pro(const float* __restrict__ pro) {
    int i = blockIdx.x * 256 + threadIdx.x;
    if (i >= N_INST * HDIM) return;
    bfsplit(pro[i], g_proh[i], g_prol[i]);
}

__global__ void __launch_bounds__(256)
prep_trans(const float* __restrict__ src, __nv_bfloat16* __restrict__ dh,
           __nv_bfloat16* __restrict__ dl, int K, int N) {
    __shared__ float t[32][33];
    const int kb = blockIdx.y * 32, nb = blockIdx.x * 32;
    const int tx = threadIdx.x & 31, ty = threadIdx.x >> 5;
#pragma unroll
    for (int j = 0; j < 32; j += 8)
        t[ty + j][tx] = src[(size_t)(kb + ty + j) * N + nb + tx];
    __syncthreads();
#pragma unroll
    for (int j = 0; j < 32; j += 8) {
        float x = t[tx][ty + j];
        size_t o = (size_t)(nb + ty + j) * K + kb + tx;
        bfsplit(x, dh[o], dl[o]);
    }
}

// ---------------------------------------------------------------------------
// bf16 mma.sync GEMM, 3-pass hi/lo, ldmatrix fragments, 4-stage cp.async.
// Output: f32 C (if Ch==null) or bf16 hi/lo split pair (Ch, Cl).
// ---------------------------------------------------------------------------
#define LDT   40
#define TILEB (128 * LDT * 2)
#define STGB  (2 * TILEB)
#define NSTG  4
#define GM_SMEM (NSTG * STGB)         // 81920 B

__global__ void __launch_bounds__(256, 2)
gemm_mma(const __nv_bfloat16* __restrict__ Ah, const __nv_bfloat16* __restrict__ Al, int lda,
         const __nv_bfloat16* __restrict__ Bh, const __nv_bfloat16* __restrict__ Bl, int ldb,
         float* __restrict__ C, __nv_bfloat16* __restrict__ Ch, __nv_bfloat16* __restrict__ Cl,
         int ldc, size_t zStride, int kLen, const float* __restrict__ bias)
{
    extern __shared__ char sm[];
    const uint32_t sb = smem_u32(sm);
    const int tid = threadIdx.x;
    const int wid = tid >> 5, lane = tid & 31;
    const int lg = lane >> 2, tg = lane & 3;
    const int wm = wid & 1, wn = wid >> 1;
    const int mBase = blockIdx.y * 128, nBase = blockIdx.x * 128;
    const int kOff = blockIdx.z * kLen;
    if (C) C += (size_t)blockIdx.z * zStride;

    const int nCh = kLen >> 5;
    const int T = 3 * nCh;

    int lp = 0, lc = 0;
    auto issue = [&](int slot) {
        const __nv_bfloat16* A = (lp < 2) ? Ah : Al;
        const __nv_bfloat16* B = (lp == 1) ? Bl : Bh;
        const int kpos = kOff + lc * 32;
        const uint32_t stg = sb + slot * STGB;
#pragma unroll
        for (int j = 0; j < 2; j++) {
            int idx = tid + 256 * j;
            int row = idx >> 2, k8 = idx & 3;
            const __nv_bfloat16* sa = A + (size_t)(mBase + row) * lda + kpos + k8 * 8;
            const __nv_bfloat16* sbp = B + (size_t)(nBase + row) * ldb + kpos + k8 * 8;
            CP16(stg + row * 80 + k8 * 16, sa);
            CP16(stg + TILEB + row * 80 + k8 * 16, sbp);
        }
        if (++lc == nCh) { lc = 0; ++lp; }
    };

    const uint32_t aSel = (uint32_t)(wm * 64 + (lane & 7) + ((lane >> 3) & 1) * 8) * 80
                        + ((lane >> 4) & 1) * 16;
    const uint32_t bSel = (uint32_t)(wn * 32 + (lane & 7) + ((lane >> 4) & 1) * 8) * 80
                        + ((lane >> 3) & 1) * 16;

    float acc[4][4][4];
#pragma unroll
    for (int i = 0; i < 4; i++)
#pragma unroll
        for (int j = 0; j < 4; j++)
#pragma unroll
            for (int k = 0; k < 4; k++) acc[i][j][k] = 0.f;

#pragma unroll
    for (int s = 0; s < NSTG - 1; s++) {
        if (lp < 3) issue(s);
        CP_COMMIT();
    }

    for (int g = 0; g < T; g++) {
        CP_WAIT2();
        __syncthreads();
        if (lp < 3) issue((g + NSTG - 1) & (NSTG - 1));
        CP_COMMIT();

        const uint32_t stgu = sb + (g & (NSTG - 1)) * STGB;
#pragma unroll
        for (int ks = 0; ks < 2; ks++) {
            uint32_t af[4][4], bfr[4][2];
#pragma unroll
            for (int mf = 0; mf < 4; mf++) {
                uint32_t addr = stgu + aSel + mf * (16 * 80) + ks * 32;
                LDMX4(af[mf][0], af[mf][1], af[mf][2], af[mf][3], addr);
            }
#pragma unroll
            for (int nfp = 0; nfp < 2; nfp++) {
                uint32_t addr = stgu + TILEB + bSel + nfp * (16 * 80) + ks * 32;
                LDMX4(bfr[2 * nfp][0], bfr[2 * nfp][1],
                      bfr[2 * nfp + 1][0], bfr[2 * nfp + 1][1], addr);
            }
#pragma unroll
            for (int mf = 0; mf < 4; mf++)
#pragma unroll
                for (int nf = 0; nf < 4; nf++)
                    MMA16816(acc[mf][nf], af[mf], bfr[nf]);
        }
    }

#pragma unroll
    for (int mf = 0; mf < 4; mf++) {
        int r0 = mBase + wm * 64 + mf * 16 + lg;
        int r1 = r0 + 8;
#pragma unroll
        for (int nf = 0; nf < 4; nf++) {
            int col = nBase + wn * 32 + nf * 8 + 2 * tg;
            float b0 = 0.f, b1 = 0.f;
            if (bias) { b0 = bias[col]; b1 = bias[col + 1]; }
            float v00 = acc[mf][nf][0] + b0, v01 = acc[mf][nf][1] + b1;
            float v10 = acc[mf][nf][2] + b0, v11 = acc[mf][nf][3] + b1;
            if (Ch) {
                __nv_bfloat162 h2, l2;
                bfsplit(v00, h2.x, l2.x); bfsplit(v01, h2.y, l2.y);
                *(__nv_bfloat162*)&Ch[(size_t)r0 * ldc + col] = h2;
                *(__nv_bfloat162*)&Cl[(size_t)r0 * ldc + col] = l2;
                bfsplit(v10, h2.x, l2.x); bfsplit(v11, h2.y, l2.y);
                *(__nv_bfloat162*)&Ch[(size_t)r1 * ldc + col] = h2;
                *(__nv_bfloat162*)&Cl[(size_t)r1 * ldc + col] = l2;
            } else {
                *(float2*)&C[(size_t)r0 * ldc + col] = make_float2(v00, v01);
                *(float2*)&C[(size_t)r1 * ldc + col] = make_float2(v10, v11);
            }
        }
    }
}

// ---------------------------------------------------------------------------
// Fused dynamic conv on tensor cores.
// bmm1: f1(64x64) = feats(64x256) @ p1(256x64), 3-pass bf16 hi/lo, LN_D, relu
// bmm2: f2(64x256) = f1(64x64) @ p2(64x256),   3-pass bf16 hi/lo, LN_H, relu
// A rows padded 49->64 by address clamp; stores predicated to r<49.
// ---------------------------------------------------------------------------
#define DCS_FEH 0            // feats hi: 49 rows x 528 B (264 bf16)
#define DCS_FEL 25872
#define DCS_SP  51744        // staged B quarter: 64 rows x 144 B, hi+lo
#define DCS_SPC 9216
#define DCS_F1  70176        // f1 f32: 49 x 272 B (68 floats)
#define DCS_F1H 83504        // f1 hi bf16: 49 x 144 B
#define DCS_F1L 90560
#define DCS_TOT 97616
#define DCS_F2  0            // f2 f32: 49 x 1056 B (aliases feats, dead by then)

__global__ void __launch_bounds__(256, 2)
dynconv_mma(const float* __restrict__ roi,
            const float* __restrict__ g1, const float* __restrict__ b1,
            const float* __restrict__ g2, const float* __restrict__ b2)
{
    extern __shared__ char sm[];
    const uint32_t sb = smem_u32(sm);
    const int n = blockIdx.x;
    const int tid = threadIdx.x;
    const int lane = tid & 31, wid = tid >> 5;
    const int lg = lane >> 2, tg = lane & 3;
    const int wm = wid & 3, wn = wid >> 2;          // 4(M) x 2(N)
    const __nv_bfloat16* ph = g_prmh + (size_t)n * PARAMS_PER;
    const __nv_bfloat16* pl = g_prml + (size_t)n * PARAMS_PER;

    // ---- feats f32 -> bf16 hi/lo into smem ----
#pragma unroll 1
    for (int i = tid; i < RDIM * 64; i += 256) {
        int r = i >> 6, c4 = i & 63;
        float4 v = *(const float4*)(roi + ((size_t)r * N_INST + n) * HDIM + c4 * 4);
        __nv_bfloat162 h01, h23, l01, l23;
        bfsplit(v.x, h01.x, l01.x); bfsplit(v.y, h01.y, l01.y);
        bfsplit(v.z, h23.x, l23.x); bfsplit(v.w, h23.y, l23.y);
        uint32_t off = r * 528 + c4 * 8;
        *(uint2*)(sm + DCS_FEH + off) = make_uint2(
            *(uint32_t*)&h01, *(uint32_t*)&h23);
        *(uint2*)(sm + DCS_FEL + off) = make_uint2(
            *(uint32_t*)&l01, *(uint32_t*)&l23);
    }

    // fragment lane constants
    int arow = wm * 16 + (lane & 15);
    if (arow > 48) arow = 48;                        // clamp padded rows
    const uint32_t aKoff = ((lane >> 4) & 1) * 16;   // +8 bf16
    const int krLane = (lane & 7) + ((lane >> 3) & 1) * 8;
    const int colLane = ((lane >> 4) & 1) * 8;

    // ================= bmm1 =================
    float acc[4][4];
#pragma unroll
    for (int i = 0; i < 4; i++)
#pragma unroll
        for (int j = 0; j < 4; j++) acc[i][j] = 0.f;

#pragma unroll 1
    for (int qb = 0; qb < 4; qb++) {                 // K quarters of 64
        __syncthreads();
#pragma unroll 1
        for (int i = tid; i < 512; i += 256) {       // p1 quarter hi+lo
            int rr = i >> 3, c8 = i & 7;
            size_t src = (size_t)(qb * 64 + rr) * 64 + c8 * 8;
            *(uint4*)(sm + DCS_SP + rr * 144 + c8 * 16) = *(const uint4*)(ph + src);
            *(uint4*)(sm + DCS_SP + DCS_SPC + rr * 144 + c8 * 16) = *(const uint4*)(pl + src);
        }
        __syncthreads();
#pragma unroll 1
        for (int pass = 0; pass < 3; pass++) {
            const uint32_t aBase = sb + ((pass < 2) ? DCS_FEH : DCS_FEL);
            const uint32_t bBase = sb + DCS_SP + ((pass == 1) ? DCS_SPC : 0);
#pragma unroll
            for (int kk = 0; kk < 4; kk++) {
                uint32_t af[4], bfr[4][2];
                LDMX4(af[0], af[1], af[2], af[3],
                      aBase + arow * 528 + (qb * 64 + kk * 16) * 2 + aKoff);
                uint32_t bk = bBase + (kk * 16 + krLane) * 144;
#pragma unroll
                for (int np = 0; np < 2; np++) {
                    uint32_t addr = bk + (wn * 32 + np * 16 + colLane) * 2;
                    LDMX4T(bfr[2 * np][0], bfr[2 * np][1],
                           bfr[2 * np + 1][0], bfr[2 * np + 1][1], addr);
                }
#pragma unroll
                for (int ng = 0; ng < 4; ng++) MMA16816(acc[ng], af, bfr[ng]);
            }
        }
    }
    // store f1 frags (f32) predicated to rows < 49
    {
        int r0 = wm * 16 + lg, r1 = r0 + 8;
#pragma unroll
        for (int ng = 0; ng < 4; ng++) {
            int col = wn * 32 + ng * 8 + 2 * tg;
            if (r0 < RDIM)
                *(float2*)(sm + DCS_F1 + r0 * 272 + col * 4) = make_float2(acc[ng][0], acc[ng][1]);
            if (r1 < RDIM)
                *(float2*)(sm + DCS_F1 + r1 * 272 + col * 4) = make_float2(acc[ng][2], acc[ng][3]);
        }
    }
    __syncthreads();

    // ---- LN over D=64 + relu -> f1 bf16 hi/lo ----
    {
        float gg0 = g1[lane], gg1 = g1[lane + 32];
        float bb0 = b1[lane], bb1 = b1[lane + 32];
        for (int r = wid; r < RDIM; r += 8) {
            float v0 = *(float*)(sm + DCS_F1 + r * 272 + lane * 4);
            float v1 = *(float*)(sm + DCS_F1 + r * 272 + (lane + 32) * 4);
            float s = warp_sum(v0 + v1);
            float sq = warp_sum(v0 * v0 + v1 * v1);
            float m = s * (1.f / DDIM);
            float var = sq * (1.f / DDIM) - m * m;
            float inv = rsqrtf(var + 1e-5f);
            float o0 = fmaxf((v0 - m) * inv * gg0 + bb0, 0.f);
            float o1 = fmaxf((v1 - m) * inv * gg1 + bb1, 0.f);
            __nv_bfloat16 h, l;
            bfsplit(o0, h, l);
            *(__nv_bfloat16*)(sm + DCS_F1H + r * 144 + lane * 2) = h;
            *(__nv_bfloat16*)(sm + DCS_F1L + r * 144 + lane * 2) = l;
            bfsplit(o1, h, l);
            *(__nv_bfloat16*)(sm + DCS_F1H + r * 144 + (lane + 32) * 2) = h;
            *(__nv_bfloat16*)(sm + DCS_F1L + r * 144 + (lane + 32) * 2) = l;
        }
    }

    // ================= bmm2: 4 h-chunks of 64 =================
#pragma unroll 1
    for (int hc = 0; hc < 4; hc++) {
        __syncthreads();
#pragma unroll 1
        for (int i = tid; i < 512; i += 256) {       // p2 chunk hi+lo
            int rr = i >> 3, c8 = i & 7;
            size_t src = (size_t)16384 + (size_t)rr * 256 + hc * 64 + c8 * 8;
            *(uint4*)(sm + DCS_SP + rr * 144 + c8 * 16) = *(const uint4*)(ph + src);
            *(uint4*)(sm + DCS_SP + DCS_SPC + rr * 144 + c8 * 16) = *(const uint4*)(pl + src);
        }
        __syncthreads();
        float ac2[4][4];
#pragma unroll
        for (int i = 0; i < 4; i++)
#pragma unroll
            for (int j = 0; j < 4; j++) ac2[i][j] = 0.f;
#pragma unroll 1
        for (int pass = 0; pass < 3; pass++) {
            const uint32_t aBase = sb + ((pass < 2) ? DCS_F1H : DCS_F1L);
            const uint32_t bBase = sb + DCS_SP + ((pass == 1) ? DCS_SPC : 0);
#pragma unroll
            for (int kk = 0; kk < 4; kk++) {
                uint32_t af[4], bfr[4][2];
                LDMX4(af[0], af[1], af[2], af[3],
                      aBase + arow * 144 + kk * 32 + aKoff);
                uint32_t bk = bBase + (kk * 16 + krLane) * 144;
#pragma unroll
                for (int np = 0; np < 2; np++) {
                    uint32_t addr = bk + (wn * 32 + np * 16 + colLane) * 2;
                    LDMX4T(bfr[2 * np][0], bfr[2 * np][1],
                           bfr[2 * np + 1][0], bfr[2 * np + 1][1], addr);
                }
#pragma unroll
                for (int ng = 0; ng < 4; ng++) MMA16816(ac2[ng], af, bfr[ng]);
            }
        }
        // store chunk to f2 f32 (aliases feats region; feats dead)
        int r0 = wm * 16 + lg, r1 = r0 + 8;
#pragma unroll
        for (int ng = 0; ng < 4; ng++) {
            int col = hc * 64 + wn * 32 + ng * 8 + 2 * tg;
            if (r0 < RDIM)
                *(float2*)(sm + DCS_F2 + r0 * 1056 + col * 4) = make_float2(ac2[ng][0], ac2[ng][1]);
            if (r1 < RDIM)
                *(float2*)(sm + DCS_F2 + r1 * 1056 + col * 4) = make_float2(ac2[ng][2], ac2[ng][3]);
        }
    }
    __syncthreads();

    // ---- LN over H=256 + relu -> g_f2h/g_f2l ----
    {
        float gA[8], bA[8];
#pragma unroll
        for (int j = 0; j < 8; j++) { gA[j] = g2[lane + 32 * j]; bA[j] = b2[lane + 32 * j]; }
        __nv_bfloat16* dh = g_f2h + (size_t)n * F2_COLS;
        __nv_bfloat16* dl = g_f2l + (size_t)n * F2_COLS;
        for (int r = wid; r < RDIM; r += 8) {
            float v[8];
            float s = 0.f, sq = 0.f;
#pragma unroll
            for (int j = 0; j < 8; j++) {
                v[j] = *(float*)(sm + DCS_F2 + r * 1056 + (lane + 32 * j) * 4);
                s += v[j]; sq += v[j] * v[j];
            }
            s = warp_sum(s); sq = warp_sum(sq);
            float m = s * (1.f / HDIM);
            float var = sq * (1.f / HDIM) - m * m;
            float inv = rsqrtf(var + 1e-5f);
#pragma unroll
            for (int j = 0; j < 8; j++) {
                int h = lane + 32 * j;
                float o = fmaxf((v[j] - m) * inv * gA[j] + bA[j], 0.f);
                bfsplit(o, dh[r * HDIM + h], dl[r * HDIM + h]);
            }
        }
    }
}

// ---------------------------------------------------------------------------
// Reduce split-K partials + bias, LN over H + relu -> out (2000 x 256)
// ---------------------------------------------------------------------------
__global__ void __launch_bounds__(256)
reduce_ln3(const float* __restrict__ b_out,
           const float* __restrict__ g3, const float* __restrict__ b3,
           float* __restrict__ out)
{
    const int lane = threadIdx.x & 31;
    const int warp = threadIdx.x >> 5;
    const int row = blockIdx.x * 8 + warp;
    float v[8];
    float s = 0.f, sq = 0.f;
#pragma unroll
    for (int j = 0; j < 8; j++) {
        int h = lane + 32 * j;
        float a = b_out[h];
#pragma unroll
        for (int z = 0; z < KSPL; z++)
            a += g_kpart[((size_t)z * MPAD + row) * HDIM + h];
        v[j] = a; s += a; sq += a * a;
    }
    s = warp_sum(s); sq = warp_sum(sq);
    float m = s * (1.f / HDIM);
    float var = sq * (1.f / HDIM) - m * m;
    float inv = rsqrtf(var + 1e-5f);
#pragma unroll
    for (int j = 0; j < 8; j++) {
        int h = lane + 32 * j;
        float o = (v[j] - m) * inv * g3[h] + b3[h];
        out[(size_t)row * HDIM + h] = fmaxf(o, 0.f);
    }
}

// ---------------------------------------------------------------------------
extern "C" void kernel_launch(void* const* d_in, const int* in_sizes, int n_in,
                              void* d_out, int out_size)
{
    (void)in_sizes; (void)n_in; (void)out_size;
    const float* pro   = (const float*)d_in[0];
    const float* roi   = (const float*)d_in[1];
    const float* W_dyn = (const float*)d_in[2];
    const float* b_dyn = (const float*)d_in[3];
    const float* W_out = (const float*)d_in[4];
    const float* b_out = (const float*)d_in[5];
    const float* g1 = (const float*)d_in[6];
    const float* b1 = (const float*)d_in[7];
    const float* g2 = (const float*)d_in[8];
    const float* b2 = (const float*)d_in[9];
    const float* g3 = (const float*)d_in[10];
    const float* b3 = (const float*)d_in[11];
    float* out = (float*)d_out;

    float* p_kpart = nullptr;
    __nv_bfloat16 *p_prmh, *p_prml, *p_wdh, *p_wdl, *p_woh, *p_wol;
    __nv_bfloat16 *p_proh, *p_prol, *p_f2h, *p_f2l;
    cudaGetSymbolAddress((void**)&p_kpart, g_kpart);
    cudaGetSymbolAddress((void**)&p_prmh, g_prmh);
    cudaGetSymbolAddress((void**)&p_prml, g_prml);
    cudaGetSymbolAddress((void**)&p_proh, g_proh);
    cudaGetSymbolAddress((void**)&p_prol, g_prol);
    cudaGetSymbolAddress((void**)&p_wdh, g_wdh);
    cudaGetSymbolAddress((void**)&p_wdl, g_wdl);
    cudaGetSymbolAddress((void**)&p_woh, g_woh);
    cudaGetSymbolAddress((void**)&p_wol, g_wol);
    cudaGetSymbolAddress((void**)&p_f2h, g_f2h);
    cudaGetSymbolAddress((void**)&p_f2l, g_f2l);

    cudaFuncSetAttribute(dynconv_mma,
                         cudaFuncAttributeMaxDynamicSharedMemorySize, DCS_TOT);
    cudaFuncSetAttribute(gemm_mma,
                         cudaFuncAttributeMaxDynamicSharedMemorySize, GM_SMEM);

    // P0: hi/lo splits + K-major transposes
    prep_pro<<<(N_INST * HDIM + 255) / 256, 256>>>(pro);
    prep_trans<<<dim3(PARAMS_PER / 32, HDIM / 32), 256>>>(W_dyn, p_wdh, p_wdl, HDIM, PARAMS_PER);
    prep_trans<<<dim3(HDIM / 32, F2_COLS / 32), 256>>>(W_out, p_woh, p_wol, F2_COLS, HDIM);

    // K1: params = pro @ W_dyn + b_dyn -> bf16 hi/lo directly
    gemm_mma<<<dim3(PARAMS_PER / 128, MPAD / 128, 1), 256, GM_SMEM>>>(
        p_proh, p_prol, HDIM, p_wdh, p_wdl, HDIM,
        nullptr, p_prmh, p_prml, PARAMS_PER, 0, HDIM, b_dyn);

    // K2: fused dynamic conv on tensor cores -> f2 hi/lo
    dynconv_mma<<<N_INST, 256, DCS_TOT>>>(roi, g1, b1, g2, b2);

    // K3: partials of F2 @ W_out, split-K=14 (f32 partials)
    gemm_mma<<<dim3(HDIM / 128, MPAD / 128, KSPL), 256, GM_SMEM>>>(
        p_f2h, p_f2l, F2_COLS, p_woh, p_wol, F2_COLS,
        p_kpart, nullptr, nullptr, HDIM, (size_t)MPAD * HDIM, KPERZ, nullptr);

    // K4: reduce + bias + LN + relu -> out
    reduce_ln3<<<N_INST / 8, 256>>>(b_out, g3, b3, out);
}

// round 15
// speedup vs baseline: 2.6186x; 1.0866x over previous
#include <cuda_runtime.h>
#include <cuda_bf16.h>
#include <cstdint>
#include <cstddef>

#define N_INST 2000
#define MPAD   2048
#define HDIM   256
#define DDIM   64
#define RDIM   49
#define PARAMS_PER 32768
#define F2_COLS 12544
#define KSPL 14
#define KPERZ (F2_COLS / KSPL)   // 896

// Scratch: __device__ globals (zero-initialized; bf16 A rows [2000,2048) stay 0)
__device__ __align__(256) __nv_bfloat16 g_prmh[(size_t)MPAD * PARAMS_PER];
__device__ __align__(256) __nv_bfloat16 g_prml[(size_t)MPAD * PARAMS_PER];
__device__ __align__(256) __nv_bfloat16 g_proh[MPAD * HDIM];
__device__ __align__(256) __nv_bfloat16 g_prol[MPAD * HDIM];
__device__ __align__(256) __nv_bfloat16 g_wdh[(size_t)PARAMS_PER * HDIM];
__device__ __align__(256) __nv_bfloat16 g_wdl[(size_t)PARAMS_PER * HDIM];
__device__ __align__(256) __nv_bfloat16 g_woh[(size_t)HDIM * F2_COLS];
__device__ __align__(256) __nv_bfloat16 g_wol[(size_t)HDIM * F2_COLS];
__device__ __align__(256) __nv_bfloat16 g_f2h[(size_t)MPAD * F2_COLS];
__device__ __align__(256) __nv_bfloat16 g_f2l[(size_t)MPAD * F2_COLS];
__device__ __align__(256) float g_kpart[(size_t)KSPL * MPAD * HDIM];

// ---------------- small helpers ----------------
__device__ __forceinline__ float warp_sum(float v) {
#pragma unroll
    for (int o = 16; o > 0; o >>= 1) v += __shfl_xor_sync(0xffffffffu, v, o);
    return v;
}
__device__ __forceinline__ void bfsplit(float x, __nv_bfloat16& h, __nv_bfloat16& l) {
    h = __float2bfloat16(x);
    l = __float2bfloat16(x - __bfloat162float(h));
}
__device__ __forceinline__ uint32_t smem_u32(const void* p) {
    uint32_t a;
    asm("{ .reg .u64 t; cvta.to.shared.u64 t, %1; cvt.u32.u64 %0, t; }" : "=r"(a) : "l"(p));
    return a;
}
#define CP16(dst, src) asm volatile( \
    "cp.async.cg.shared.global [%0], [%1], 16;" :: "r"(dst), "l"(src) : "memory")
#define CP_COMMIT() asm volatile("cp.async.commit_group;" ::: "memory")
#define CP_WAIT2()  asm volatile("cp.async.wait_group 2;" ::: "memory")

#define MMA16816(c, a, b) asm volatile( \
    "mma.sync.aligned.m16n8k16.row.col.f32.bf16.bf16.f32 " \
    "{%0,%1,%2,%3}, {%4,%5,%6,%7}, {%8,%9}, {%0,%1,%2,%3};" \
    : "+f"((c)[0]), "+f"((c)[1]), "+f"((c)[2]), "+f"((c)[3]) \
    : "r"((a)[0]), "r"((a)[1]), "r"((a)[2]), "r"((a)[3]), "r"((b)[0]), "r"((b)[1]))

#define LDMX4(r0, r1, r2, r3, addr) asm volatile( \
    "ldmatrix.sync.aligned.m8n8.x4.shared.b16 {%0,%1,%2,%3}, [%4];" \
    : "=r"(r0), "=r"(r1), "=r"(r2), "=r"(r3) : "r"(addr))
#define LDMX4T(r0, r1, r2, r3, addr) asm volatile( \
    "ldmatrix.sync.aligned.m8n8.x4.trans.shared.b16 {%0,%1,%2,%3}, [%4];" \
    : "=r"(r0), "=r"(r1), "=r"(r2), "=r"(r3) : "r"(addr))

// ---------------------------------------------------------------------------
// Prep kernels
// ---------------------------------------------------------------------------
__global__ void prep_pro(const float* __restrict__ pro) {
    int i = blockIdx.x * 256 + threadIdx.x;
    if (i >= N_INST * HDIM) return;
    bfsplit(pro[i], g_proh[i], g_prol[i]);
}

__global__ void __launch_bounds__(256)
prep_trans(const float* __restrict__ src, __nv_bfloat16* __restrict__ dh,
           __nv_bfloat16* __restrict__ dl, int K, int N) {
    __shared__ float t[32][33];
    const int kb = blockIdx.y * 32, nb = blockIdx.x * 32;
    const int tx = threadIdx.x & 31, ty = threadIdx.x >> 5;
#pragma unroll
    for (int j = 0; j < 32; j += 8)
        t[ty + j][tx] = src[(size_t)(kb + ty + j) * N + nb + tx];
    __syncthreads();
#pragma unroll
    for (int j = 0; j < 32; j += 8) {
        float x = t[tx][ty + j];
        size_t o = (size_t)(nb + ty + j) * K + kb + tx;
        bfsplit(x, dh[o], dl[o]);
    }
}

// ---------------------------------------------------------------------------
// bf16 mma.sync GEMM, 3-pass hi/lo, ldmatrix fragments, 4-stage cp.async.
// 128 threads, 2x2 warps, 64x64 warp tile (4 MMA per LDSM.x4).
// Output: f32 C (if Ch==null) or bf16 hi/lo split pair (Ch, Cl).
// ---------------------------------------------------------------------------
#define LDT   40
#define TILEB (128 * LDT * 2)
#define STGB  (2 * TILEB)
#define NSTG  4
#define GM_SMEM (NSTG * STGB)         // 81920 B

__global__ void __launch_bounds__(128, 2)
gemm_mma(const __nv_bfloat16* __restrict__ Ah, const __nv_bfloat16* __restrict__ Al, int lda,
         const __nv_bfloat16* __restrict__ Bh, const __nv_bfloat16* __restrict__ Bl, int ldb,
         float* __restrict__ C, __nv_bfloat16* __restrict__ Ch, __nv_bfloat16* __restrict__ Cl,
         int ldc, size_t zStride, int kLen, const float* __restrict__ bias)
{
    extern __shared__ char sm[];
    const uint32_t sb = smem_u32(sm);
    const int tid = threadIdx.x;
    const int wid = tid >> 5, lane = tid & 31;
    const int lg = lane >> 2, tg = lane & 3;
    const int wm = wid & 1, wn = wid >> 1;            // 2 x 2 warp grid
    const int mBase = blockIdx.y * 128, nBase = blockIdx.x * 128;
    const int kOff = blockIdx.z * kLen;
    if (C) C += (size_t)blockIdx.z * zStride;

    const int nCh = kLen >> 5;
    const int T = 3 * nCh;

    int lp = 0, lc = 0;
    auto issue = [&](int slot) {
        const __nv_bfloat16* A = (lp < 2) ? Ah : Al;
        const __nv_bfloat16* B = (lp == 1) ? Bl : Bh;
        const int kpos = kOff + lc * 32;
        const uint32_t stg = sb + slot * STGB;
#pragma unroll
        for (int j = 0; j < 4; j++) {
            int idx = tid + 128 * j;
            int row = idx >> 2, k8 = idx & 3;
            const __nv_bfloat16* sa = A + (size_t)(mBase + row) * lda + kpos + k8 * 8;
            const __nv_bfloat16* sbp = B + (size_t)(nBase + row) * ldb + kpos + k8 * 8;
            CP16(stg + row * 80 + k8 * 16, sa);
            CP16(stg + TILEB + row * 80 + k8 * 16, sbp);
        }
        if (++lc == nCh) { lc = 0; ++lp; }
    };

    const uint32_t aSel = (uint32_t)(wm * 64 + (lane & 7) + ((lane >> 3) & 1) * 8) * 80
                        + ((lane >> 4) & 1) * 16;
    const uint32_t bSel = (uint32_t)(wn * 64 + (lane & 7) + ((lane >> 4) & 1) * 8) * 80
                        + ((lane >> 3) & 1) * 16;

    float acc[4][8][4];
#pragma unroll
    for (int i = 0; i < 4; i++)
#pragma unroll
        for (int j = 0; j < 8; j++)
#pragma unroll
            for (int k = 0; k < 4; k++) acc[i][j][k] = 0.f;

#pragma unroll
    for (int s = 0; s < NSTG - 1; s++) {
        if (lp < 3) issue(s);
        CP_COMMIT();
    }

    for (int g = 0; g < T; g++) {
        CP_WAIT2();
        __syncthreads();
        if (lp < 3) issue((g + NSTG - 1) & (NSTG - 1));
        CP_COMMIT();

        const uint32_t stgu = sb + (g & (NSTG - 1)) * STGB;
#pragma unroll
        for (int ks = 0; ks < 2; ks++) {
            uint32_t af[4][4], bfr[8][2];
#pragma unroll
            for (int mf = 0; mf < 4; mf++) {
                uint32_t addr = stgu + aSel + mf * (16 * 80) + ks * 32;
                LDMX4(af[mf][0], af[mf][1], af[mf][2], af[mf][3], addr);
            }
#pragma unroll
            for (int nfp = 0; nfp < 4; nfp++) {
                uint32_t addr = stgu + TILEB + bSel + nfp * (16 * 80) + ks * 32;
                LDMX4(bfr[2 * nfp][0], bfr[2 * nfp][1],
                      bfr[2 * nfp + 1][0], bfr[2 * nfp + 1][1], addr);
            }
#pragma unroll
            for (int mf = 0; mf < 4; mf++)
#pragma unroll
                for (int nf = 0; nf < 8; nf++)
                    MMA16816(acc[mf][nf], af[mf], bfr[nf]);
        }
    }

#pragma unroll
    for (int mf = 0; mf < 4; mf++) {
        int r0 = mBase + wm * 64 + mf * 16 + lg;
        int r1 = r0 + 8;
#pragma unroll
        for (int nf = 0; nf < 8; nf++) {
            int col = nBase + wn * 64 + nf * 8 + 2 * tg;
            float b0 = 0.f, b1 = 0.f;
            if (bias) { b0 = bias[col]; b1 = bias[col + 1]; }
            float v00 = acc[mf][nf][0] + b0, v01 = acc[mf][nf][1] + b1;
            float v10 = acc[mf][nf][2] + b0, v11 = acc[mf][nf][3] + b1;
            if (Ch) {
                __nv_bfloat162 h2, l2;
                bfsplit(v00, h2.x, l2.x); bfsplit(v01, h2.y, l2.y);
                *(__nv_bfloat162*)&Ch[(size_t)r0 * ldc + col] = h2;
                *(__nv_bfloat162*)&Cl[(size_t)r0 * ldc + col] = l2;
                bfsplit(v10, h2.x, l2.x); bfsplit(v11, h2.y, l2.y);
                *(__nv_bfloat162*)&Ch[(size_t)r1 * ldc + col] = h2;
                *(__nv_bfloat162*)&Cl[(size_t)r1 * ldc + col] = l2;
            } else {
                *(float2*)&C[(size_t)r0 * ldc + col] = make_float2(v00, v01);
                *(float2*)&C[(size_t)r1 * ldc + col] = make_float2(v10, v11);
            }
        }
    }
}

// ---------------------------------------------------------------------------
// Fused dynamic conv on tensor cores (unchanged from round 13).
// ---------------------------------------------------------------------------
#define DCS_FEH 0
#define DCS_FEL 25872
#define DCS_SP  51744
#define DCS_SPC 9216
#define DCS_F1  70176
#define DCS_F1H 83504
#define DCS_F1L 90560
#define DCS_TOT 97616
#define DCS_F2  0

__global__ void __launch_bounds__(256, 2)
dynconv_mma(const float* __restrict__ roi,
            const float* __restrict__ g1, const float* __restrict__ b1,
            const float* __restrict__ g2, const float* __restrict__ b2)
{
    extern __shared__ char sm[];
    const uint32_t sb = smem_u32(sm);
    const int n = blockIdx.x;
    const int tid = threadIdx.x;
    const int lane = tid & 31, wid = tid >> 5;
    const int lg = lane >> 2, tg = lane & 3;
    const int wm = wid & 3, wn = wid >> 2;
    const __nv_bfloat16* ph = g_prmh + (size_t)n * PARAMS_PER;
    const __nv_bfloat16* pl = g_prml + (size_t)n * PARAMS_PER;

#pragma unroll 1
    for (int i = tid; i < RDIM * 64; i += 256) {
        int r = i >> 6, c4 = i & 63;
        float4 v = *(const float4*)(roi + ((size_t)r * N_INST + n) * HDIM + c4 * 4);
        __nv_bfloat162 h01, h23, l01, l23;
        bfsplit(v.x, h01.x, l01.x); bfsplit(v.y, h01.y, l01.y);
        bfsplit(v.z, h23.x, l23.x); bfsplit(v.w, h23.y, l23.y);
        uint32_t off = r * 528 + c4 * 8;
        *(uint2*)(sm + DCS_FEH + off) = make_uint2(*(uint32_t*)&h01, *(uint32_t*)&h23);
        *(uint2*)(sm + DCS_FEL + off) = make_uint2(*(uint32_t*)&l01, *(uint32_t*)&l23);
    }

    int arow = wm * 16 + (lane & 15);
    if (arow > 48) arow = 48;
    const uint32_t aKoff = ((lane >> 4) & 1) * 16;
    const int krLane = (lane & 7) + ((lane >> 3) & 1) * 8;
    const int colLane = ((lane >> 4) & 1) * 8;

    // ================= bmm1 =================
    float acc[4][4];
#pragma unroll
    for (int i = 0; i < 4; i++)
#pragma unroll
        for (int j = 0; j < 4; j++) acc[i][j] = 0.f;

#pragma unroll 1
    for (int qb = 0; qb < 4; qb++) {
        __syncthreads();
#pragma unroll 1
        for (int i = tid; i < 512; i += 256) {
            int rr = i >> 3, c8 = i & 7;
            size_t src = (size_t)(qb * 64 + rr) * 64 + c8 * 8;
            *(uint4*)(sm + DCS_SP + rr * 144 + c8 * 16) = *(const uint4*)(ph + src);
            *(uint4*)(sm + DCS_SP + DCS_SPC + rr * 144 + c8 * 16) = *(const uint4*)(pl + src);
        }
        __syncthreads();
#pragma unroll 1
        for (int pass = 0; pass < 3; pass++) {
            const uint32_t aBase = sb + ((pass < 2) ? DCS_FEH : DCS_FEL);
            const uint32_t bBase = sb + DCS_SP + ((pass == 1) ? DCS_SPC : 0);
#pragma unroll
            for (int kk = 0; kk < 4; kk++) {
                uint32_t af[4], bfr[4][2];
                LDMX4(af[0], af[1], af[2], af[3],
                      aBase + arow * 528 + (qb * 64 + kk * 16) * 2 + aKoff);
                uint32_t bk = bBase + (kk * 16 + krLane) * 144;
#pragma unroll
                for (int np = 0; np < 2; np++) {
                    uint32_t addr = bk + (wn * 32 + np * 16 + colLane) * 2;
                    LDMX4T(bfr[2 * np][0], bfr[2 * np][1],
                           bfr[2 * np + 1][0], bfr[2 * np + 1][1], addr);
                }
#pragma unroll
                for (int ng = 0; ng < 4; ng++) MMA16816(acc[ng], af, bfr[ng]);
            }
        }
    }
    {
        int r0 = wm * 16 + lg, r1 = r0 + 8;
#pragma unroll
        for (int ng = 0; ng < 4; ng++) {
            int col = wn * 32 + ng * 8 + 2 * tg;
            if (r0 < RDIM)
                *(float2*)(sm + DCS_F1 + r0 * 272 + col * 4) = make_float2(acc[ng][0], acc[ng][1]);
            if (r1 < RDIM)
                *(float2*)(sm + DCS_F1 + r1 * 272 + col * 4) = make_float2(acc[ng][2], acc[ng][3]);
        }
    }
    __syncthreads();

    // ---- LN over D=64 + relu -> f1 bf16 hi/lo ----
    {
        float gg0 = g1[lane], gg1 = g1[lane + 32];
        float bb0 = b1[lane], bb1 = b1[lane + 32];
        for (int r = wid; r < RDIM; r += 8) {
            float v0 = *(float*)(sm + DCS_F1 + r * 272 + lane * 4);
            float v1 = *(float*)(sm + DCS_F1 + r * 272 + (lane + 32) * 4);
            float s = warp_sum(v0 + v1);
            float sq = warp_sum(v0 * v0 + v1 * v1);
            float m = s * (1.f / DDIM);
            float var = sq * (1.f / DDIM) - m * m;
            float inv = rsqrtf(var + 1e-5f);
            float o0 = fmaxf((v0 - m) * inv * gg0 + bb0, 0.f);
            float o1 = fmaxf((v1 - m) * inv * gg1 + bb1, 0.f);
            __nv_bfloat16 h, l;
            bfsplit(o0, h, l);
            *(__nv_bfloat16*)(sm + DCS_F1H + r * 144 + lane * 2) = h;
            *(__nv_bfloat16*)(sm + DCS_F1L + r * 144 + lane * 2) = l;
            bfsplit(o1, h, l);
            *(__nv_bfloat16*)(sm + DCS_F1H + r * 144 + (lane + 32) * 2) = h;
            *(__nv_bfloat16*)(sm + DCS_F1L + r * 144 + (lane + 32) * 2) = l;
        }
    }

    // ================= bmm2: 4 h-chunks of 64 =================
#pragma unroll 1
    for (int hc = 0; hc < 4; hc++) {
        __syncthreads();
#pragma unroll 1
        for (int i = tid; i < 512; i += 256) {
            int rr = i >> 3, c8 = i & 7;
            size_t src = (size_t)16384 + (size_t)rr * 256 + hc * 64 + c8 * 8;
            *(uint4*)(sm + DCS_SP + rr * 144 + c8 * 16) = *(const uint4*)(ph + src);
            *(uint4*)(sm + DCS_SP + DCS_SPC + rr * 144 + c8 * 16) = *(const uint4*)(pl + src);
        }
        __syncthreads();
        float ac2[4][4];
#pragma unroll
        for (int i = 0; i < 4; i++)
#pragma unroll
            for (int j = 0; j < 4; j++) ac2[i][j] = 0.f;
#pragma unroll 1
        for (int pass = 0; pass < 3; pass++) {
            const uint32_t aBase = sb + ((pass < 2) ? DCS_F1H : DCS_F1L);
            const uint32_t bBase = sb + DCS_SP + ((pass == 1) ? DCS_SPC : 0);
#pragma unroll
            for (int kk = 0; kk < 4; kk++) {
                uint32_t af[4], bfr[4][2];
                LDMX4(af[0], af[1], af[2], af[3],
                      aBase + arow * 144 + kk * 32 + aKoff);
                uint32_t bk = bBase + (kk * 16 + krLane) * 144;
#pragma unroll
                for (int np = 0; np < 2; np++) {
                    uint32_t addr = bk + (wn * 32 + np * 16 + colLane) * 2;
                    LDMX4T(bfr[2 * np][0], bfr[2 * np][1],
                           bfr[2 * np + 1][0], bfr[2 * np + 1][1], addr);
                }
#pragma unroll
                for (int ng = 0; ng < 4; ng++) MMA16816(ac2[ng], af, bfr[ng]);
            }
        }
        int r0 = wm * 16 + lg, r1 = r0 + 8;
#pragma unroll
        for (int ng = 0; ng < 4; ng++) {
            int col = hc * 64 + wn * 32 + ng * 8 + 2 * tg;
            if (r0 < RDIM)
                *(float2*)(sm + DCS_F2 + r0 * 1056 + col * 4) = make_float2(ac2[ng][0], ac2[ng][1]);
            if (r1 < RDIM)
                *(float2*)(sm + DCS_F2 + r1 * 1056 + col * 4) = make_float2(ac2[ng][2], ac2[ng][3]);
        }
    }
    __syncthreads();

    // ---- LN over H=256 + relu -> g_f2h/g_f2l ----
    {
        float gA[8], bA[8];
#pragma unroll
        for (int j = 0; j < 8; j++) { gA[j] = g2[lane + 32 * j]; bA[j] = b2[lane + 32 * j]; }
        __nv_bfloat16* dh = g_f2h + (size_t)n * F2_COLS;
        __nv_bfloat16* dl = g_f2l + (size_t)n * F2_COLS;
        for (int r = wid; r < RDIM; r += 8) {
            float v[8];
            float s = 0.f, sq = 0.f;
#pragma unroll
            for (int j = 0; j < 8; j++) {
                v[j] = *(float*)(sm + DCS_F2 + r * 1056 + (lane + 32 * j) * 4);
                s += v[j]; sq += v[j] * v[j];
            }
            s = warp_sum(s); sq = warp_sum(sq);
            float m = s * (1.f / HDIM);
            float var = sq * (1.f / HDIM) - m * m;
            float inv = rsqrtf(var + 1e-5f);
#pragma unroll
            for (int j = 0; j < 8; j++) {
                int h = lane + 32 * j;
                float o = fmaxf((v[j] - m) * inv * gA[j] + bA[j], 0.f);
                bfsplit(o, dh[r * HDIM + h], dl[r * HDIM + h]);
            }
        }
    }
}

// ---------------------------------------------------------------------------
// Reduce split-K partials + bias, LN over H + relu -> out (2000 x 256)
// ---------------------------------------------------------------------------
__global__ void __launch_bounds__(256)
reduce_ln3(const float* __restrict__ b_out,
           const float* __restrict__ g3, const float* __restrict__ b3,
           float* __restrict__ out)
{
    const int lane = threadIdx.x & 31;
    const int warp = threadIdx.x >> 5;
    const int row = blockIdx.x * 8 + warp;
    float v[8];
    float s = 0.f, sq = 0.f;
#pragma unroll
    for (int j = 0; j < 8; j++) {
        int h = lane + 32 * j;
        float a = b_out[h];
#pragma unroll
        for (int z = 0; z < KSPL; z++)
            a += g_kpart[((size_t)z * MPAD + row) * HDIM + h];
        v[j] = a; s += a; sq += a * a;
    }
    s = warp_sum(s); sq = warp_sum(sq);
    float m = s * (1.f / HDIM);
    float var = sq * (1.f / HDIM) - m * m;
    float inv = rsqrtf(var + 1e-5f);
#pragma unroll
    for (int j = 0; j < 8; j++) {
        int h = lane + 32 * j;
        float o = (v[j] - m) * inv * g3[h] + b3[h];
        out[(size_t)row * HDIM + h] = fmaxf(o, 0.f);
    }
}

// ---------------------------------------------------------------------------
extern "C" void kernel_launch(void* const* d_in, const int* in_sizes, int n_in,
                              void* d_out, int out_size)
{
    (void)in_sizes; (void)n_in; (void)out_size;
    const float* pro   = (const float*)d_in[0];
    const float* roi   = (const float*)d_in[1];
    const float* W_dyn = (const float*)d_in[2];
    const float* b_dyn = (const float*)d_in[3];
    const float* W_out = (const float*)d_in[4];
    const float* b_out = (const float*)d_in[5];
    const float* g1 = (const float*)d_in[6];
    const float* b1 = (const float*)d_in[7];
    const float* g2 = (const float*)d_in[8];
    const float* b2 = (const float*)d_in[9];
    const float* g3 = (const float*)d_in[10];
    const float* b3 = (const float*)d_in[11];
    float* out = (float*)d_out;

    float* p_kpart = nullptr;
    __nv_bfloat16 *p_prmh, *p_prml, *p_wdh, *p_wdl, *p_woh, *p_wol;
    __nv_bfloat16 *p_proh, *p_prol, *p_f2h, *p_f2l;
    cudaGetSymbolAddress((void**)&p_kpart, g_kpart);
    cudaGetSymbolAddress((void**)&p_prmh, g_prmh);
    cudaGetSymbolAddress((void**)&p_prml, g_prml);
    cudaGetSymbolAddress((void**)&p_proh, g_proh);
    cudaGetSymbolAddress((void**)&p_prol, g_prol);
    cudaGetSymbolAddress((void**)&p_wdh, g_wdh);
    cudaGetSymbolAddress((void**)&p_wdl, g_wdl);
    cudaGetSymbolAddress((void**)&p_woh, g_woh);
    cudaGetSymbolAddress((void**)&p_wol, g_wol);
    cudaGetSymbolAddress((void**)&p_f2h, g_f2h);
    cudaGetSymbolAddress((void**)&p_f2l, g_f2l);

    cudaFuncSetAttribute(dynconv_mma,
                         cudaFuncAttributeMaxDynamicSharedMemorySize, DCS_TOT);
    cudaFuncSetAttribute(gemm_mma,
                         cudaFuncAttributeMaxDynamicSharedMemorySize, GM_SMEM);

    // P0: hi/lo splits + K-major transposes
    prep_pro<<<(N_INST * HDIM + 255) / 256, 256>>>(pro);
    prep_trans<<<dim3(PARAMS_PER / 32, HDIM / 32), 256>>>(W_dyn, p_wdh, p_wdl, HDIM, PARAMS_PER);
    prep_trans<<<dim3(HDIM / 32, F2_COLS / 32), 256>>>(W_out, p_woh, p_wol, F2_COLS, HDIM);

    // K1: params = pro @ W_dyn + b_dyn -> bf16 hi/lo directly
    gemm_mma<<<dim3(PARAMS_PER / 128, MPAD / 128, 1), 128, GM_SMEM>>>(
        p_proh, p_prol, HDIM, p_wdh, p_wdl, HDIM,
        nullptr, p_prmh, p_prml, PARAMS_PER, 0, HDIM, b_dyn);

    // K2: fused dynamic conv on tensor cores -> f2 hi/lo
    dynconv_mma<<<N_INST, 256, DCS_TOT>>>(roi, g1, b1, g2, b2);

    // K3: partials of F2 @ W_out, split-K=14 (f32 partials)
    gemm_mma<<<dim3(HDIM / 128, MPAD / 128, KSPL), 128, GM_SMEM>>>(
        p_f2h, p_f2l, F2_COLS, p_woh, p_wol, F2_COLS,
        p_kpart, nullptr, nullptr, HDIM, (size_t)MPAD * HDIM, KPERZ, nullptr);

    // K4: reduce + bias + LN + relu -> out
    reduce_ln3<<<N_INST / 8, 256>>>(b_out, g3, b3, out);
}